// round 10
// baseline (speedup 1.0000x reference)
#include <cuda_runtime.h>
#include <math.h>
#include <cstdint>

#define Bn 8
#define Ln 4096
#define Dn 1024
#define Hn 16
#define O3 3072

// ---------------- scratch (static device globals; no allocation) ----------------
__device__ __align__(256) float g_qkv[(size_t)Bn * O3 * Ln];   // (B,3072,L) tf32, compact cols
__device__ __align__(256) float g_qT[(size_t)Bn * Ln * Dn];    // (B,Lc,1024) tf32
__device__ __align__(256) float g_x32[(size_t)Bn * Ln * Dn];   // compacted+rounded x
__device__ __align__(256) float g_w32[(size_t)O3 * Dn];        // rounded w_qkv
__device__ __align__(256) float g_ctx[Bn * Hn * 64 * 64];
__device__ __align__(256) float g_weff[(size_t)Bn * Dn * Dn];
__device__ int g_idx[Bn][Ln];    // compact j -> original l
__device__ int g_rank[Bn][Ln];   // original l -> compact j or -1
__device__ int g_Lc[Bn];
__device__ int g_Lcp256[Bn];
__device__ int g_Lcp128[Bn];

// ---------------- helpers ----------------
__device__ __forceinline__ uint32_t smem_u32(const void* p) {
    uint32_t a;
    asm("{ .reg .u64 t; cvta.to.shared.u64 t, %1; cvt.u32.u64 %0, t; }" : "=r"(a) : "l"(p));
    return a;
}
__device__ __forceinline__ float tf32r(float v) {
    uint32_t o;
    asm("cvt.rna.tf32.f32 %0, %1;" : "=r"(o) : "f"(v));
    return __uint_as_float(o);
}
__device__ __forceinline__ void cpasync16(uint32_t dst, const void* src) {
    asm volatile("cp.async.cg.shared.global [%0], [%1], 16;" :: "r"(dst), "l"(src) : "memory");
}
#define CP_COMMIT() asm volatile("cp.async.commit_group;" ::: "memory")
#define CP_WAIT0()  asm volatile("cp.async.wait_group 0;" ::: "memory")

__device__ __forceinline__ void mma8(float* c, uint32_t a0, uint32_t a1, uint32_t a2, uint32_t a3,
                                     uint32_t b0, uint32_t b1) {
    asm volatile("mma.sync.aligned.m16n8k8.row.col.f32.tf32.tf32.f32 "
        "{%0,%1,%2,%3}, {%4,%5,%6,%7}, {%8,%9}, {%0,%1,%2,%3};"
        : "+f"(c[0]), "+f"(c[1]), "+f"(c[2]), "+f"(c[3])
        : "r"(a0), "r"(a1), "r"(a2), "r"(a3), "r"(b0), "r"(b1));
}
__device__ __forceinline__ uint32_t fu(float v) { return __float_as_uint(v); }
__device__ __forceinline__ bool mask_at(const void* m, int idx, int u8) {
    if (u8) return ((const unsigned char*)m)[idx] != 0;
    return ((const int*)m)[idx] != 0;
}

// ---------------- count (with fused u8/i32 layout detection) ----------------
__global__ __launch_bounds__(256) void count_kernel(const void* __restrict__ mask) {
    const int b = blockIdx.x, tid = threadIdx.x;
    __shared__ int found;
    if (tid == 0) found = 0;
    __syncthreads();
    {
        const unsigned char* mb = (const unsigned char*)mask;
        int local = 0;
        for (int i = tid; i < 4096; i += 256)
            if ((i & 3) && mb[i]) local = 1;
        if (local) atomicOr(&found, 1);
    }
    __syncthreads();
    const int u8 = found;

    __shared__ int cnt[256];
    __shared__ int excl[257];
    int loc[16], c = 0;
#pragma unroll
    for (int t = 0; t < 16; t++) {
        const int l = tid * 16 + t;
        loc[t] = mask_at(mask, b * Ln + l, u8) ? 0 : 1;
        c += loc[t];
    }
    cnt[tid] = c;
    __syncthreads();
    if (tid == 0) {
        int s = 0;
        for (int i = 0; i < 256; i++) { excl[i] = s; s += cnt[i]; }
        excl[256] = s;
        g_Lc[b] = s;
        g_Lcp256[b] = (s + 255) & ~255;
        g_Lcp128[b] = (s + 127) & ~127;
    }
    __syncthreads();
    int j = excl[tid];
#pragma unroll
    for (int t = 0; t < 16; t++) {
        const int l = tid * 16 + t;
        if (loc[t]) { g_idx[b][j] = l; g_rank[b][l] = j; j++; }
        else g_rank[b][l] = -1;
    }
}

// ---------------- prep: rounded w; compacted+rounded x (zero pad) ----------------
__global__ __launch_bounds__(256) void prep_w(const float4* __restrict__ w) {
    const int r = blockIdx.x, tid = threadIdx.x;
    float4 v = w[(size_t)r * 256 + tid];
    v.x = tf32r(v.x); v.y = tf32r(v.y); v.z = tf32r(v.z); v.w = tf32r(v.w);
    ((float4*)g_w32)[(size_t)r * 256 + tid] = v;
}

__global__ __launch_bounds__(256) void prep_x(const float4* __restrict__ x) {
    const int b = blockIdx.y, j = blockIdx.x, tid = threadIdx.x;
    if (j >= g_Lcp256[b]) return;
    float4* dst = (float4*)g_x32 + ((size_t)b * Ln + j) * 256;
    if (j >= g_Lc[b]) { dst[tid] = make_float4(0.f, 0.f, 0.f, 0.f); return; }
    const int l = g_idx[b][j];
    float4 v = x[((size_t)b * Ln + l) * 256 + tid];
    v.x = tf32r(v.x); v.y = tf32r(v.y); v.z = tf32r(v.z); v.w = tf32r(v.w);
    dst[tid] = v;
}

// ---------------- GEMM: C(M x N) = A(M x K) @ B(N x K)^T ----------------
// Tiles 128x128x32, 2 CTA/SM, double buffer with SINGLE barrier per iteration,
// k-interleaved LDS.64, row stride 40 (conflict-free).
// MODE 0: n-limited (GEMM1), tf32-round output to C.
// MODE 1: m-limited (GEMM2), bias + scatter rows via g_idx into C (= final out).
#define RS 40
#define STGF ((128 + 128) * RS)    // 10240 floats / stage
#define SMG (2 * STGF * 4)         // 81920 B

template <int MODE>
__global__ __launch_bounds__(256, 2) void gemm_tc(
    const float* __restrict__ Aall, const float* __restrict__ Ball,
    float* __restrict__ Call, const float* __restrict__ bias,
    int K, int ldc, size_t bsA, size_t bsB, size_t bsC) {
    const int b = blockIdx.z;
    const int m0 = blockIdx.x * 128, n0 = blockIdx.y * 128;
    if (MODE == 0) { if (n0 >= g_Lcp128[b]) return; }
    else           { if (m0 >= g_Lcp128[b]) return; }

    extern __shared__ float sm[];
    const uint32_t smb = smem_u32(sm);
    const int tid = threadIdx.x, lane = tid & 31, wid = tid >> 5;
    const float* A = Aall + bsA * b;
    const float* Bp = Ball + bsB * b;
    float* C = Call + bsC * b;

    const int g = lane >> 2, t4 = lane & 3;
    const int warpM = wid & 1, warpN = wid >> 1;      // 2 x 4 warps
    const int mrow0 = warpM * 64, ncol0 = warpN * 32; // warp tile 64 x 32

    float acc[4][4][4];
#pragma unroll
    for (int mf = 0; mf < 4; mf++)
#pragma unroll
        for (int nf = 0; nf < 4; nf++)
#pragma unroll
            for (int j = 0; j < 4; j++) acc[mf][nf][j] = 0.f;

    auto load_stage = [&](int s, int ko) {
        const uint32_t sb = smb + (uint32_t)(s * STGF) * 4;
        const int row = tid >> 1, kh = (tid & 1) * 16;
        const float* srcA = A + (size_t)(m0 + row) * K + ko + kh;
        const float* srcB = Bp + (size_t)(n0 + row) * K + ko + kh;
        const uint32_t dA = sb + (uint32_t)(row * RS + kh) * 4;
        const uint32_t dB = sb + (uint32_t)((128 + row) * RS + kh) * 4;
#pragma unroll
        for (int j = 0; j < 4; j++) {
            cpasync16(dA + j * 16, srcA + j * 4);
            cpasync16(dB + j * 16, srcB + j * 4);
        }
    };

    const int NIT = K >> 5;
    load_stage(0, 0);
    CP_COMMIT();

    for (int i = 0; i < NIT; i++) {
        CP_WAIT0();          // stage i complete (own writes; barrier publishes all)
        __syncthreads();     // single barrier: stage i visible, stage i-1 slot free
        if (i + 1 < NIT) { load_stage((i + 1) & 1, (i + 1) * 32); CP_COMMIT(); }

        const float* As = sm + (i & 1) * STGF;
        const float* Bs = As + 128 * RS;
#pragma unroll
        for (int kk = 0; kk < 32; kk += 8) {
            float2 alo[4], ahi[4];
#pragma unroll
            for (int mf = 0; mf < 4; mf++) {
                const float* ap = As + (mrow0 + mf * 16 + g) * RS + kk + 2 * t4;
                alo[mf] = *(const float2*)ap;
                ahi[mf] = *(const float2*)(ap + 8 * RS);
            }
#pragma unroll
            for (int nf = 0; nf < 4; nf++) {
                const float2 bv = *(const float2*)(Bs + (ncol0 + nf * 8 + g) * RS + kk + 2 * t4);
                const uint32_t b0 = fu(bv.x), b1 = fu(bv.y);
#pragma unroll
                for (int mf = 0; mf < 4; mf++)
                    mma8(acc[mf][nf], fu(alo[mf].x), fu(ahi[mf].x), fu(alo[mf].y), fu(ahi[mf].y), b0, b1);
            }
        }
    }

    if (MODE == 0) {
#pragma unroll
        for (int mf = 0; mf < 4; mf++) {
            const int r0 = m0 + mrow0 + mf * 16 + g;
#pragma unroll
            for (int nf = 0; nf < 4; nf++) {
                const int c0 = n0 + ncol0 + nf * 8 + 2 * t4;
                float2 v0 = make_float2(tf32r(acc[mf][nf][0]), tf32r(acc[mf][nf][1]));
                float2 v1 = make_float2(tf32r(acc[mf][nf][2]), tf32r(acc[mf][nf][3]));
                *(float2*)(C + (size_t)r0 * ldc + c0) = v0;
                *(float2*)(C + (size_t)(r0 + 8) * ldc + c0) = v1;
            }
        }
    } else {
        const int lc = g_Lc[b];
#pragma unroll
        for (int mf = 0; mf < 4; mf++) {
            const int r0 = m0 + mrow0 + mf * 16 + g;
            const int la = (r0 < lc) ? g_idx[b][r0] : -1;
            const int lb2 = (r0 + 8 < lc) ? g_idx[b][r0 + 8] : -1;
#pragma unroll
            for (int nf = 0; nf < 4; nf++) {
                const int c0 = n0 + ncol0 + nf * 8 + 2 * t4;
                const float2 bb = *(const float2*)(bias + c0);
                if (la >= 0) {
                    float2 v0 = make_float2(acc[mf][nf][0] + bb.x, acc[mf][nf][1] + bb.y);
                    *(float2*)(C + (size_t)la * ldc + c0) = v0;
                }
                if (lb2 >= 0) {
                    float2 v1 = make_float2(acc[mf][nf][2] + bb.x, acc[mf][nf][3] + bb.y);
                    *(float2*)(C + (size_t)lb2 * ldc + c0) = v1;
                }
            }
        }
    }
}

// ---------------- fill masked rows of out with bias ----------------
__global__ __launch_bounds__(256) void fill_bias(const float4* __restrict__ bout,
                                                 float4* __restrict__ out) {
    const int b = blockIdx.y, l = blockIdx.x, tid = threadIdx.x;
    if (g_rank[b][l] >= 0) return;
    out[((size_t)b * Ln + l) * 256 + tid] = bout[tid];
}

// ---------------- softmax on k rows over compact cols; zeroes g_ctx + pad ----------------
__global__ __launch_bounds__(256) void softmax_kernel() {
    const int b = blockIdx.y, r = blockIdx.x;
    const int tid = threadIdx.x;
    {
        const int gid = ((blockIdx.y * 1024 + blockIdx.x) << 8) + tid;
        if (gid < Bn * Hn * 64 * 64) g_ctx[gid] = 0.f;
    }
    const int lc = g_Lc[b], lcp = g_Lcp256[b];
    float* rowp = g_qkv + (size_t)b * O3 * Ln + (size_t)(1024 + r) * Ln;
    float sum = 0.f;
    for (int l = tid; l < lc; l += 256) sum += expf(rowp[l]);
    __shared__ float red[256];
    red[tid] = sum;
    __syncthreads();
    for (int s = 128; s > 0; s >>= 1) {
        if (tid < s) red[tid] += red[tid + s];
        __syncthreads();
    }
    const float inv = 1.f / red[0];
    for (int l = tid; l < lcp; l += 256)
        rowp[l] = (l < lc) ? tf32r(expf(rowp[l]) * inv) : 0.f;
}

// ---------------- context: chunks of 256 compact cols, 128x128, single-barrier 2-stage ----------------
#define CSTGF (2 * 128 * RS)
#define SMC (2 * CSTGF * 4)   // 81920 B

__global__ __launch_bounds__(256, 2) void ctx_tc() {
    const int b = blockIdx.z, hp = blockIdx.x, ch = blockIdx.y;
    const int l0 = ch * 256;
    if (l0 >= g_Lcp256[b]) return;

    extern __shared__ float sm[];
    const uint32_t smb = smem_u32(sm);
    const int tid = threadIdx.x, lane = tid & 31, wid = tid >> 5;
    const float* A = g_qkv + (size_t)b * O3 * Ln + (size_t)(1024 + hp * 128) * Ln + l0;
    const float* Bp = g_qkv + (size_t)b * O3 * Ln + (size_t)(2048 + hp * 128) * Ln + l0;

    const int g = lane >> 2, t4 = lane & 3;
    const int warpM = wid & 1, warpN = wid >> 1;
    const int mrow0 = warpM * 64, ncol0 = warpN * 32;

    float acc[4][4][4];
#pragma unroll
    for (int mf = 0; mf < 4; mf++)
#pragma unroll
        for (int nf = 0; nf < 4; nf++)
#pragma unroll
            for (int j = 0; j < 4; j++) acc[mf][nf][j] = 0.f;

    auto load_stage = [&](int s, int ko) {
        const uint32_t sb = smb + (uint32_t)(s * CSTGF) * 4;
        const int row = tid >> 1, kh = (tid & 1) * 16;
        const float* srcA = A + (size_t)row * Ln + ko + kh;
        const float* srcB = Bp + (size_t)row * Ln + ko + kh;
        const uint32_t dA = sb + (uint32_t)(row * RS + kh) * 4;
        const uint32_t dB = sb + (uint32_t)((128 + row) * RS + kh) * 4;
#pragma unroll
        for (int j = 0; j < 4; j++) {
            cpasync16(dA + j * 16, srcA + j * 4);
            cpasync16(dB + j * 16, srcB + j * 4);
        }
    };

    const int NIT = 8;   // 256 / 32
    load_stage(0, 0);
    CP_COMMIT();

    for (int i = 0; i < NIT; i++) {
        CP_WAIT0();
        __syncthreads();
        if (i + 1 < NIT) { load_stage((i + 1) & 1, (i + 1) * 32); CP_COMMIT(); }

        const float* As = sm + (i & 1) * CSTGF;
        const float* Bs = As + 128 * RS;
#pragma unroll
        for (int kk = 0; kk < 32; kk += 8) {
            float2 alo[4], ahi[4];
#pragma unroll
            for (int mf = 0; mf < 4; mf++) {
                const float* ap = As + (mrow0 + mf * 16 + g) * RS + kk + 2 * t4;
                alo[mf] = *(const float2*)ap;
                ahi[mf] = *(const float2*)(ap + 8 * RS);
            }
#pragma unroll
            for (int nf = 0; nf < 4; nf++) {
                const float2 bv = *(const float2*)(Bs + (ncol0 + nf * 8 + g) * RS + kk + 2 * t4);
                const uint32_t b0 = fu(bv.x), b1 = fu(bv.y);
#pragma unroll
                for (int mf = 0; mf < 4; mf++)
                    mma8(acc[mf][nf], fu(alo[mf].x), fu(ahi[mf].x), fu(alo[mf].y), fu(ahi[mf].y), b0, b1);
            }
        }
    }

    if (warpM == (warpN >> 1)) {
        const int h = hp * 2 + warpM;
        float* cp = g_ctx + (size_t)(b * Hn + h) * 64 * 64;
#pragma unroll
        for (int mf = 0; mf < 4; mf++) {
            const int d0 = mf * 16 + g;
#pragma unroll
            for (int nf = 0; nf < 4; nf++) {
                const int e0 = (warpN & 1) * 32 + nf * 8 + 2 * t4;
                atomicAdd(cp + (size_t)d0 * 64 + e0, acc[mf][nf][0]);
                atomicAdd(cp + (size_t)d0 * 64 + e0 + 1, acc[mf][nf][1]);
                atomicAdd(cp + (size_t)(d0 + 8) * 64 + e0, acc[mf][nf][2]);
                atomicAdd(cp + (size_t)(d0 + 8) * 64 + e0 + 1, acc[mf][nf][3]);
            }
        }
    }
}

// ---------------- weff (SIMT, f32 in, tf32 out) ----------------
__global__ __launch_bounds__(256) void weff_kernel(const float* __restrict__ wout) {
    __shared__ float Ws[64][65];
    __shared__ float Cs[64][68];
    const int b = blockIdx.z, h = blockIdx.y, o0 = blockIdx.x * 64;
    const int tid = threadIdx.x;
    const int rr = tid >> 2;
    const int q4 = (tid & 3) * 16;
    const float* wp = wout + (size_t)(o0 + rr) * Dn + h * 64 + q4;
#pragma unroll
    for (int j = 0; j < 16; j += 4) {
        float4 t4v = *(const float4*)(wp + j);
        Ws[q4 + j + 0][rr] = t4v.x; Ws[q4 + j + 1][rr] = t4v.y;
        Ws[q4 + j + 2][rr] = t4v.z; Ws[q4 + j + 3][rr] = t4v.w;
    }
    const float* cp = g_ctx + ((size_t)(b * Hn + h) * 64 + rr) * 64 + q4;
#pragma unroll
    for (int j = 0; j < 16; j += 4) *(float4*)&Cs[rr][q4 + j] = *(const float4*)(cp + j);
    __syncthreads();

    const int oo = tid >> 2, eg = tid & 3;
    float acc[16];
#pragma unroll
    for (int j = 0; j < 16; j++) acc[j] = 0.f;
#pragma unroll 8
    for (int dd = 0; dd < 64; dd++) {
        const float wv = Ws[dd][oo];
#pragma unroll
        for (int j = 0; j < 16; j++) acc[j] = fmaf(wv, Cs[dd][eg * 16 + j], acc[j]);
    }
    float* op = g_weff + (size_t)b * Dn * Dn + (size_t)(o0 + oo) * Dn + h * 64 + eg * 16;
#pragma unroll
    for (int j = 0; j < 16; j += 4)
        *(float4*)(op + j) = make_float4(tf32r(acc[j]), tf32r(acc[j + 1]),
                                         tf32r(acc[j + 2]), tf32r(acc[j + 3]));
}

// ---------------- transpose q -> qT (compact rows, 0.125 scale) ----------------
__global__ __launch_bounds__(256) void transpose_q() {
    const int b = blockIdx.z, l0 = blockIdx.x * 32, c0 = blockIdx.y * 32;
    if (l0 >= g_Lcp128[b]) return;
    __shared__ float t[32][33];
    const int tx = threadIdx.x & 31, ty = threadIdx.x >> 5;
    const float* q = g_qkv + (size_t)b * O3 * Ln;
#pragma unroll
    for (int k = 0; k < 4; k++)
        t[ty + 8 * k][tx] = q[(size_t)(c0 + ty + 8 * k) * Ln + l0 + tx];
    __syncthreads();
#pragma unroll
    for (int k = 0; k < 4; k++) {
        const int l = l0 + ty + 8 * k;
        g_qT[((size_t)b * Ln + l) * Dn + c0 + tx] = 0.125f * t[tx][ty + 8 * k];
    }
}

// ---------------- host side ----------------
extern "C" void kernel_launch(void* const* d_in, const int* in_sizes, int n_in,
                              void* d_out, int out_size) {
    const float* x = (const float*)d_in[0];
    const void* masks = d_in[1];
    const float* w_qkv = (const float*)d_in[2];
    const float* w_out = (const float*)d_in[3];
    const float* b_out = (const float*)d_in[4];
    float* out = (float*)d_out;

    void *pQ, *pQT, *pWE, *pX, *pW;
    cudaGetSymbolAddress(&pQ, g_qkv);
    cudaGetSymbolAddress(&pQT, g_qT);
    cudaGetSymbolAddress(&pWE, g_weff);
    cudaGetSymbolAddress(&pX, g_x32);
    cudaGetSymbolAddress(&pW, g_w32);

    cudaFuncSetAttribute(gemm_tc<0>, cudaFuncAttributeMaxDynamicSharedMemorySize, SMG);
    cudaFuncSetAttribute(gemm_tc<1>, cudaFuncAttributeMaxDynamicSharedMemorySize, SMG);
    cudaFuncSetAttribute(ctx_tc, cudaFuncAttributeMaxDynamicSharedMemorySize, SMC);

    count_kernel<<<Bn, 256>>>(masks);                    // launch 1
    prep_w<<<O3, 256>>>((const float4*)w_qkv);           // launch 2
    prep_x<<<dim3(Ln, Bn), 256>>>((const float4*)x);     // launch 3

    // GEMM1 (launch 4 -> ncu target): g_qkv[b](3072 x Lcp) = g_w32 @ g_x32[b]^T
    gemm_tc<0><<<dim3(24, 32, Bn), 256, SMG>>>(
        (const float*)pW, (const float*)pX, (float*)pQ, nullptr,
        Dn, Ln, (size_t)0, (size_t)Ln * Dn, (size_t)O3 * Ln);

    fill_bias<<<dim3(Ln, Bn), 256>>>((const float4*)b_out, (float4*)out);

    softmax_kernel<<<dim3(1024, Bn), 256>>>();

    ctx_tc<<<dim3(8, 16, Bn), 256, SMC>>>();

    weff_kernel<<<dim3(16, Hn, Bn), 256>>>(w_out);

    transpose_q<<<dim3(128, 32, Bn), 256>>>();

    // GEMM2: out rows (scattered via g_idx) = g_qT[b] @ g_weff[b]^T + b_out
    gemm_tc<1><<<dim3(32, 8, Bn), 256, SMG>>>(
        (const float*)pQT, (const float*)pWE, out, b_out,
        Dn, Dn, (size_t)Ln * Dn, (size_t)Dn * Dn, (size_t)Ln * Dn);
}

// round 11
// speedup vs baseline: 1.5398x; 1.5398x over previous
#include <cuda_runtime.h>
#include <math.h>
#include <cstdint>

#define Bn 8
#define Ln 4096
#define Dn 1024
#define Hn 16
#define O3 3072

// ---------------- scratch (static device globals; no allocation) ----------------
__device__ __align__(256) float g_qkv[(size_t)Bn * O3 * Ln];   // (B,3072,L) tf32, compact cols
__device__ __align__(256) float g_qT[(size_t)Bn * Ln * Dn];    // (B,Lc,1024) tf32
__device__ __align__(256) float g_x32[(size_t)Bn * Ln * Dn];   // compacted+rounded x
__device__ __align__(256) float g_w32[(size_t)O3 * Dn];        // rounded w_qkv
__device__ __align__(256) float g_ctx[Bn * Hn * 64 * 64];
__device__ __align__(256) float g_weff[(size_t)Bn * Dn * Dn];
__device__ int g_idx[Bn][Ln];    // compact j -> original l
__device__ int g_rank[Bn][Ln];   // original l -> compact j or -1
__device__ int g_Lc[Bn];
__device__ int g_Lcp256[Bn];
__device__ int g_Lcp128[Bn];

// ---------------- helpers ----------------
__device__ __forceinline__ uint32_t smem_u32(const void* p) {
    uint32_t a;
    asm("{ .reg .u64 t; cvta.to.shared.u64 t, %1; cvt.u32.u64 %0, t; }" : "=r"(a) : "l"(p));
    return a;
}
__device__ __forceinline__ float tf32r(float v) {
    uint32_t o;
    asm("cvt.rna.tf32.f32 %0, %1;" : "=r"(o) : "f"(v));
    return __uint_as_float(o);
}
__device__ __forceinline__ void cpasync16(uint32_t dst, const void* src) {
    asm volatile("cp.async.cg.shared.global [%0], [%1], 16;" :: "r"(dst), "l"(src) : "memory");
}
#define CP_COMMIT() asm volatile("cp.async.commit_group;" ::: "memory")
#define CP_WAIT1()  asm volatile("cp.async.wait_group 1;" ::: "memory")
#define CP_WAIT0()  asm volatile("cp.async.wait_group 0;" ::: "memory")

__device__ __forceinline__ void mma8(float* c, uint32_t a0, uint32_t a1, uint32_t a2, uint32_t a3,
                                     uint32_t b0, uint32_t b1) {
    asm volatile("mma.sync.aligned.m16n8k8.row.col.f32.tf32.tf32.f32 "
        "{%0,%1,%2,%3}, {%4,%5,%6,%7}, {%8,%9}, {%0,%1,%2,%3};"
        : "+f"(c[0]), "+f"(c[1]), "+f"(c[2]), "+f"(c[3])
        : "r"(a0), "r"(a1), "r"(a2), "r"(a3), "r"(b0), "r"(b1));
}
__device__ __forceinline__ uint32_t fu(float v) { return __float_as_uint(v); }
__device__ __forceinline__ bool mask_at(const void* m, int idx, int u8) {
    if (u8) return ((const unsigned char*)m)[idx] != 0;
    return ((const int*)m)[idx] != 0;
}

// ---------------- count (with fused u8/i32 layout detection) ----------------
__global__ __launch_bounds__(256) void count_kernel(const void* __restrict__ mask) {
    const int b = blockIdx.x, tid = threadIdx.x;
    __shared__ int found;
    if (tid == 0) found = 0;
    __syncthreads();
    {
        const unsigned char* mb = (const unsigned char*)mask;
        int local = 0;
        for (int i = tid; i < 4096; i += 256)
            if ((i & 3) && mb[i]) local = 1;
        if (local) atomicOr(&found, 1);
    }
    __syncthreads();
    const int u8 = found;

    __shared__ int cnt[256];
    __shared__ int excl[257];
    int loc[16], c = 0;
#pragma unroll
    for (int t = 0; t < 16; t++) {
        const int l = tid * 16 + t;
        loc[t] = mask_at(mask, b * Ln + l, u8) ? 0 : 1;
        c += loc[t];
    }
    cnt[tid] = c;
    __syncthreads();
    if (tid == 0) {
        int s = 0;
        for (int i = 0; i < 256; i++) { excl[i] = s; s += cnt[i]; }
        excl[256] = s;
        g_Lc[b] = s;
        g_Lcp256[b] = (s + 255) & ~255;
        g_Lcp128[b] = (s + 127) & ~127;
    }
    __syncthreads();
    int j = excl[tid];
#pragma unroll
    for (int t = 0; t < 16; t++) {
        const int l = tid * 16 + t;
        if (loc[t]) { g_idx[b][j] = l; g_rank[b][l] = j; j++; }
        else g_rank[b][l] = -1;
    }
}

// ---------------- prep: rounded w; compacted+rounded x (zero pad) ----------------
__global__ __launch_bounds__(256) void prep_w(const float4* __restrict__ w) {
    const int r = blockIdx.x, tid = threadIdx.x;
    float4 v = w[(size_t)r * 256 + tid];
    v.x = tf32r(v.x); v.y = tf32r(v.y); v.z = tf32r(v.z); v.w = tf32r(v.w);
    ((float4*)g_w32)[(size_t)r * 256 + tid] = v;
}

__global__ __launch_bounds__(256) void prep_x(const float4* __restrict__ x) {
    const int b = blockIdx.y, j = blockIdx.x, tid = threadIdx.x;
    if (j >= g_Lcp256[b]) return;
    float4* dst = (float4*)g_x32 + ((size_t)b * Ln + j) * 256;
    if (j >= g_Lc[b]) { dst[tid] = make_float4(0.f, 0.f, 0.f, 0.f); return; }
    const int l = g_idx[b][j];
    float4 v = x[((size_t)b * Ln + l) * 256 + tid];
    v.x = tf32r(v.x); v.y = tf32r(v.y); v.z = tf32r(v.z); v.w = tf32r(v.w);
    dst[tid] = v;
}

// ---------------- GEMM: C(M x N) = A(M x K) @ B(N x K)^T ----------------
// Tiles 128x256x32, 512 threads (16 warps, warp tile 64x32), 3-stage pipeline
// (R7 ordering: wait1 -> barrier -> issue i+2 -> compute), k-interleaved LDS.64,
// row stride 40 (conflict-free). 1 CTA/SM, 4 warps/SMSP.
// MODE 0: n-limited (GEMM1), tf32-round output to C.
// MODE 1: m-limited (GEMM2), bias + scatter rows via g_idx into C (= final out).
#define RS 40
#define STGF ((128 + 256) * RS)    // 15360 floats / stage
#define NST 3
#define SMG (NST * STGF * 4)       // 184320 B

template <int MODE>
__global__ __launch_bounds__(512, 1) void gemm_tc(
    const float* __restrict__ Aall, const float* __restrict__ Ball,
    float* __restrict__ Call, const float* __restrict__ bias,
    int K, int ldc, size_t bsA, size_t bsB, size_t bsC) {
    const int b = blockIdx.z;
    const int m0 = blockIdx.x * 128, n0 = blockIdx.y * 256;
    if (MODE == 0) { if (n0 >= g_Lcp256[b]) return; }
    else           { if (m0 >= g_Lcp128[b]) return; }

    extern __shared__ float sm[];
    const uint32_t smb = smem_u32(sm);
    const int tid = threadIdx.x, lane = tid & 31, wid = tid >> 5;
    const float* A = Aall + bsA * b;
    const float* Bp = Ball + bsB * b;
    float* C = Call + bsC * b;

    const int g = lane >> 2, t4 = lane & 3;
    const int warpM = wid & 1, warpN = wid >> 1;      // 2 x 8 warps
    const int mrow0 = warpM * 64, ncol0 = warpN * 32; // warp tile 64 x 32

    float acc[4][4][4];
#pragma unroll
    for (int mf = 0; mf < 4; mf++)
#pragma unroll
        for (int nf = 0; nf < 4; nf++)
#pragma unroll
            for (int j = 0; j < 4; j++) acc[mf][nf][j] = 0.f;

    auto load_stage = [&](int s, int ko) {
        const uint32_t sb = smb + (uint32_t)(s * STGF) * 4;
        {   // A: 128 rows x 32 k, 4 threads/row (2 chunks each)
            const int row = tid >> 2, c2 = (tid & 3) * 8;
            const float* src = A + (size_t)(m0 + row) * K + ko + c2;
            const uint32_t dst = sb + (uint32_t)(row * RS + c2) * 4;
            cpasync16(dst, src);
            cpasync16(dst + 16, src + 4);
        }
        {   // B: 256 rows x 32 k, 2 threads/row (16 floats each)
            const int row = tid & 255, kh = (tid >> 8) * 16;
            const float* src = Bp + (size_t)(n0 + row) * K + ko + kh;
            const uint32_t dst = sb + (uint32_t)((128 + row) * RS + kh) * 4;
#pragma unroll
            for (int j = 0; j < 4; j++) cpasync16(dst + j * 16, src + j * 4);
        }
    };

    const int NIT = K >> 5;
    load_stage(0, 0);  CP_COMMIT();
    load_stage(1, 32); CP_COMMIT();

    for (int i = 0; i < NIT; i++) {
        CP_WAIT1();          // oldest (stage i) complete; stage i+1 stays in flight
        __syncthreads();
        if (i + 2 < NIT) load_stage((i + 2) % NST, (i + 2) * 32);
        CP_COMMIT();

        const float* As = sm + (i % NST) * STGF;
        const float* Bs = As + 128 * RS;
#pragma unroll
        for (int kk = 0; kk < 32; kk += 8) {
            float2 alo[4], ahi[4];
#pragma unroll
            for (int mf = 0; mf < 4; mf++) {
                const float* ap = As + (mrow0 + mf * 16 + g) * RS + kk + 2 * t4;
                alo[mf] = *(const float2*)ap;
                ahi[mf] = *(const float2*)(ap + 8 * RS);
            }
#pragma unroll
            for (int nf = 0; nf < 4; nf++) {
                const float2 bv = *(const float2*)(Bs + (ncol0 + nf * 8 + g) * RS + kk + 2 * t4);
                const uint32_t b0 = fu(bv.x), b1 = fu(bv.y);
#pragma unroll
                for (int mf = 0; mf < 4; mf++)
                    mma8(acc[mf][nf], fu(alo[mf].x), fu(ahi[mf].x), fu(alo[mf].y), fu(ahi[mf].y), b0, b1);
            }
        }
    }

    if (MODE == 0) {
#pragma unroll
        for (int mf = 0; mf < 4; mf++) {
            const int r0 = m0 + mrow0 + mf * 16 + g;
#pragma unroll
            for (int nf = 0; nf < 4; nf++) {
                const int c0 = n0 + ncol0 + nf * 8 + 2 * t4;
                float2 v0 = make_float2(tf32r(acc[mf][nf][0]), tf32r(acc[mf][nf][1]));
                float2 v1 = make_float2(tf32r(acc[mf][nf][2]), tf32r(acc[mf][nf][3]));
                *(float2*)(C + (size_t)r0 * ldc + c0) = v0;
                *(float2*)(C + (size_t)(r0 + 8) * ldc + c0) = v1;
            }
        }
    } else {
        const int lc = g_Lc[b];
#pragma unroll
        for (int mf = 0; mf < 4; mf++) {
            const int r0 = m0 + mrow0 + mf * 16 + g;
            const int la = (r0 < lc) ? g_idx[b][r0] : -1;
            const int lb2 = (r0 + 8 < lc) ? g_idx[b][r0 + 8] : -1;
#pragma unroll
            for (int nf = 0; nf < 4; nf++) {
                const int c0 = n0 + ncol0 + nf * 8 + 2 * t4;
                const float2 bb = *(const float2*)(bias + c0);
                if (la >= 0) {
                    float2 v0 = make_float2(acc[mf][nf][0] + bb.x, acc[mf][nf][1] + bb.y);
                    *(float2*)(C + (size_t)la * ldc + c0) = v0;
                }
                if (lb2 >= 0) {
                    float2 v1 = make_float2(acc[mf][nf][2] + bb.x, acc[mf][nf][3] + bb.y);
                    *(float2*)(C + (size_t)lb2 * ldc + c0) = v1;
                }
            }
        }
    }
}

// ---------------- fill masked rows of out with bias ----------------
__global__ __launch_bounds__(256) void fill_bias(const float4* __restrict__ bout,
                                                 float4* __restrict__ out) {
    const int b = blockIdx.y, l = blockIdx.x, tid = threadIdx.x;
    if (g_rank[b][l] >= 0) return;
    out[((size_t)b * Ln + l) * 256 + tid] = bout[tid];
}

// ---------------- softmax on k rows over compact cols; zeroes g_ctx + pad ----------------
__global__ __launch_bounds__(256) void softmax_kernel() {
    const int b = blockIdx.y, r = blockIdx.x;
    const int tid = threadIdx.x;
    {
        const int gid = ((blockIdx.y * 1024 + blockIdx.x) << 8) + tid;
        if (gid < Bn * Hn * 64 * 64) g_ctx[gid] = 0.f;
    }
    const int lc = g_Lc[b], lcp = g_Lcp256[b];
    float* rowp = g_qkv + (size_t)b * O3 * Ln + (size_t)(1024 + r) * Ln;
    float sum = 0.f;
    for (int l = tid; l < lc; l += 256) sum += expf(rowp[l]);
    __shared__ float red[256];
    red[tid] = sum;
    __syncthreads();
    for (int s = 128; s > 0; s >>= 1) {
        if (tid < s) red[tid] += red[tid + s];
        __syncthreads();
    }
    const float inv = 1.f / red[0];
    for (int l = tid; l < lcp; l += 256)
        rowp[l] = (l < lc) ? tf32r(expf(rowp[l]) * inv) : 0.f;
}

// ---------------- context: chunks of 256 compact cols, 128x128, 2-stage (R9 verbatim) ----------------
#define CSTGF (2 * 128 * RS)
#define SMC (2 * CSTGF * 4)   // 81920 B

__global__ __launch_bounds__(256, 2) void ctx_tc() {
    const int b = blockIdx.z, hp = blockIdx.x, ch = blockIdx.y;
    const int l0 = ch * 256;
    if (l0 >= g_Lcp256[b]) return;

    extern __shared__ float sm[];
    const uint32_t smb = smem_u32(sm);
    const int tid = threadIdx.x, lane = tid & 31, wid = tid >> 5;
    const float* A = g_qkv + (size_t)b * O3 * Ln + (size_t)(1024 + hp * 128) * Ln + l0;
    const float* Bp = g_qkv + (size_t)b * O3 * Ln + (size_t)(2048 + hp * 128) * Ln + l0;

    const int g = lane >> 2, t4 = lane & 3;
    const int warpM = wid & 1, warpN = wid >> 1;
    const int mrow0 = warpM * 64, ncol0 = warpN * 32;

    float acc[4][4][4];
#pragma unroll
    for (int mf = 0; mf < 4; mf++)
#pragma unroll
        for (int nf = 0; nf < 4; nf++)
#pragma unroll
            for (int j = 0; j < 4; j++) acc[mf][nf][j] = 0.f;

    auto load_stage = [&](int s, int ko) {
        const uint32_t sb = smb + (uint32_t)(s * CSTGF) * 4;
        const int row = tid >> 1, kh = (tid & 1) * 16;
        const float* srcA = A + (size_t)row * Ln + ko + kh;
        const float* srcB = Bp + (size_t)row * Ln + ko + kh;
        const uint32_t dA = sb + (uint32_t)(row * RS + kh) * 4;
        const uint32_t dB = sb + (uint32_t)((128 + row) * RS + kh) * 4;
#pragma unroll
        for (int j = 0; j < 4; j++) {
            cpasync16(dA + j * 16, srcA + j * 4);
            cpasync16(dB + j * 16, srcB + j * 4);
        }
    };

    const int NIT = 8;   // 256 / 32
    load_stage(0, 0);
    CP_COMMIT();

    for (int i = 0; i < NIT; i++) {
        if (i + 1 < NIT) { load_stage((i + 1) & 1, (i + 1) * 32); CP_COMMIT(); CP_WAIT1(); }
        else             { CP_WAIT0(); }
        __syncthreads();

        const float* As = sm + (i & 1) * CSTGF;
        const float* Bs = As + 128 * RS;
#pragma unroll
        for (int kk = 0; kk < 32; kk += 8) {
            float2 alo[4], ahi[4];
#pragma unroll
            for (int mf = 0; mf < 4; mf++) {
                const float* ap = As + (mrow0 + mf * 16 + g) * RS + kk + 2 * t4;
                alo[mf] = *(const float2*)ap;
                ahi[mf] = *(const float2*)(ap + 8 * RS);
            }
#pragma unroll
            for (int nf = 0; nf < 4; nf++) {
                const float2 bv = *(const float2*)(Bs + (ncol0 + nf * 8 + g) * RS + kk + 2 * t4);
                const uint32_t b0 = fu(bv.x), b1 = fu(bv.y);
#pragma unroll
                for (int mf = 0; mf < 4; mf++)
                    mma8(acc[mf][nf], fu(alo[mf].x), fu(ahi[mf].x), fu(alo[mf].y), fu(ahi[mf].y), b0, b1);
            }
        }
        __syncthreads();
    }

    if (warpM == (warpN >> 1)) {
        const int h = hp * 2 + warpM;
        float* cp = g_ctx + (size_t)(b * Hn + h) * 64 * 64;
#pragma unroll
        for (int mf = 0; mf < 4; mf++) {
            const int d0 = mf * 16 + g;
#pragma unroll
            for (int nf = 0; nf < 4; nf++) {
                const int e0 = (warpN & 1) * 32 + nf * 8 + 2 * t4;
                atomicAdd(cp + (size_t)d0 * 64 + e0, acc[mf][nf][0]);
                atomicAdd(cp + (size_t)d0 * 64 + e0 + 1, acc[mf][nf][1]);
                atomicAdd(cp + (size_t)(d0 + 8) * 64 + e0, acc[mf][nf][2]);
                atomicAdd(cp + (size_t)(d0 + 8) * 64 + e0 + 1, acc[mf][nf][3]);
            }
        }
    }
}

// ---------------- weff (SIMT, f32 in, tf32 out) ----------------
__global__ __launch_bounds__(256) void weff_kernel(const float* __restrict__ wout) {
    __shared__ float Ws[64][65];
    __shared__ float Cs[64][68];
    const int b = blockIdx.z, h = blockIdx.y, o0 = blockIdx.x * 64;
    const int tid = threadIdx.x;
    const int rr = tid >> 2;
    const int q4 = (tid & 3) * 16;
    const float* wp = wout + (size_t)(o0 + rr) * Dn + h * 64 + q4;
#pragma unroll
    for (int j = 0; j < 16; j += 4) {
        float4 t4v = *(const float4*)(wp + j);
        Ws[q4 + j + 0][rr] = t4v.x; Ws[q4 + j + 1][rr] = t4v.y;
        Ws[q4 + j + 2][rr] = t4v.z; Ws[q4 + j + 3][rr] = t4v.w;
    }
    const float* cp = g_ctx + ((size_t)(b * Hn + h) * 64 + rr) * 64 + q4;
#pragma unroll
    for (int j = 0; j < 16; j += 4) *(float4*)&Cs[rr][q4 + j] = *(const float4*)(cp + j);
    __syncthreads();

    const int oo = tid >> 2, eg = tid & 3;
    float acc[16];
#pragma unroll
    for (int j = 0; j < 16; j++) acc[j] = 0.f;
#pragma unroll 8
    for (int dd = 0; dd < 64; dd++) {
        const float wv = Ws[dd][oo];
#pragma unroll
        for (int j = 0; j < 16; j++) acc[j] = fmaf(wv, Cs[dd][eg * 16 + j], acc[j]);
    }
    float* op = g_weff + (size_t)b * Dn * Dn + (size_t)(o0 + oo) * Dn + h * 64 + eg * 16;
#pragma unroll
    for (int j = 0; j < 16; j += 4)
        *(float4*)(op + j) = make_float4(tf32r(acc[j]), tf32r(acc[j + 1]),
                                         tf32r(acc[j + 2]), tf32r(acc[j + 3]));
}

// ---------------- transpose q -> qT (compact rows, 0.125 scale) ----------------
__global__ __launch_bounds__(256) void transpose_q() {
    const int b = blockIdx.z, l0 = blockIdx.x * 32, c0 = blockIdx.y * 32;
    if (l0 >= g_Lcp128[b]) return;
    __shared__ float t[32][33];
    const int tx = threadIdx.x & 31, ty = threadIdx.x >> 5;
    const float* q = g_qkv + (size_t)b * O3 * Ln;
#pragma unroll
    for (int k = 0; k < 4; k++)
        t[ty + 8 * k][tx] = q[(size_t)(c0 + ty + 8 * k) * Ln + l0 + tx];
    __syncthreads();
#pragma unroll
    for (int k = 0; k < 4; k++) {
        const int l = l0 + ty + 8 * k;
        g_qT[((size_t)b * Ln + l) * Dn + c0 + tx] = 0.125f * t[tx][ty + 8 * k];
    }
}

// ---------------- host side ----------------
extern "C" void kernel_launch(void* const* d_in, const int* in_sizes, int n_in,
                              void* d_out, int out_size) {
    const float* x = (const float*)d_in[0];
    const void* masks = d_in[1];
    const float* w_qkv = (const float*)d_in[2];
    const float* w_out = (const float*)d_in[3];
    const float* b_out = (const float*)d_in[4];
    float* out = (float*)d_out;

    void *pQ, *pQT, *pWE, *pX, *pW;
    cudaGetSymbolAddress(&pQ, g_qkv);
    cudaGetSymbolAddress(&pQT, g_qT);
    cudaGetSymbolAddress(&pWE, g_weff);
    cudaGetSymbolAddress(&pX, g_x32);
    cudaGetSymbolAddress(&pW, g_w32);

    cudaFuncSetAttribute(gemm_tc<0>, cudaFuncAttributeMaxDynamicSharedMemorySize, SMG);
    cudaFuncSetAttribute(gemm_tc<1>, cudaFuncAttributeMaxDynamicSharedMemorySize, SMG);
    cudaFuncSetAttribute(ctx_tc, cudaFuncAttributeMaxDynamicSharedMemorySize, SMC);

    count_kernel<<<Bn, 256>>>(masks);                    // launch 1
    prep_w<<<O3, 256>>>((const float4*)w_qkv);           // launch 2
    prep_x<<<dim3(Ln, Bn), 256>>>((const float4*)x);     // launch 3

    // GEMM1 (launch 4 -> ncu target): g_qkv[b](3072 x Lcp) = g_w32 @ g_x32[b]^T
    gemm_tc<0><<<dim3(24, 16, Bn), 512, SMG>>>(
        (const float*)pW, (const float*)pX, (float*)pQ, nullptr,
        Dn, Ln, (size_t)0, (size_t)Ln * Dn, (size_t)O3 * Ln);

    fill_bias<<<dim3(Ln, Bn), 256>>>((const float4*)b_out, (float4*)out);

    softmax_kernel<<<dim3(1024, Bn), 256>>>();

    ctx_tc<<<dim3(8, 16, Bn), 256, SMC>>>();

    weff_kernel<<<dim3(16, Hn, Bn), 256>>>(w_out);

    transpose_q<<<dim3(128, 32, Bn), 256>>>();

    // GEMM2: out rows (scattered via g_idx) = g_qT[b] @ g_weff[b]^T + b_out
    gemm_tc<1><<<dim3(32, 4, Bn), 512, SMG>>>(
        (const float*)pQT, (const float*)pWE, out, b_out,
        Dn, Dn, (size_t)Ln * Dn, (size_t)Dn * Dn, (size_t)Ln * Dn);
}

// round 12
// speedup vs baseline: 1.7455x; 1.1336x over previous
#include <cuda_runtime.h>
#include <math.h>
#include <cstdint>

#define Bn 8
#define Ln 4096
#define Dn 1024
#define Hn 16
#define O3 3072

// ---------------- scratch (static device globals; no allocation) ----------------
__device__ __align__(256) float g_qkv[(size_t)Bn * O3 * Ln];   // only k,v rows used now
__device__ __align__(256) float g_qT[(size_t)Bn * Ln * Dn];    // reused: [0]=WqT, [+Dn*Dn]=M[b]
__device__ __align__(256) float g_x32[(size_t)Bn * Ln * Dn];   // compacted+rounded x
__device__ __align__(256) float g_w32[(size_t)O3 * Dn];        // rounded w_qkv
__device__ __align__(256) float g_ctx[Bn * Hn * 64 * 64];
__device__ __align__(256) float g_weff[(size_t)Bn * Dn * Dn];
__device__ int g_idx[Bn][Ln];
__device__ int g_rank[Bn][Ln];
__device__ int g_Lc[Bn];
__device__ int g_Lcp256[Bn];
__device__ int g_Lcp128[Bn];

// ---------------- helpers ----------------
__device__ __forceinline__ uint32_t smem_u32(const void* p) {
    uint32_t a;
    asm("{ .reg .u64 t; cvta.to.shared.u64 t, %1; cvt.u32.u64 %0, t; }" : "=r"(a) : "l"(p));
    return a;
}
__device__ __forceinline__ float tf32r(float v) {
    uint32_t o;
    asm("cvt.rna.tf32.f32 %0, %1;" : "=r"(o) : "f"(v));
    return __uint_as_float(o);
}
__device__ __forceinline__ void cpasync16(uint32_t dst, const void* src) {
    asm volatile("cp.async.cg.shared.global [%0], [%1], 16;" :: "r"(dst), "l"(src) : "memory");
}
#define CP_COMMIT() asm volatile("cp.async.commit_group;" ::: "memory")
#define CP_WAIT1()  asm volatile("cp.async.wait_group 1;" ::: "memory")
#define CP_WAIT0()  asm volatile("cp.async.wait_group 0;" ::: "memory")

__device__ __forceinline__ void mma8(float* c, uint32_t a0, uint32_t a1, uint32_t a2, uint32_t a3,
                                     uint32_t b0, uint32_t b1) {
    asm volatile("mma.sync.aligned.m16n8k8.row.col.f32.tf32.tf32.f32 "
        "{%0,%1,%2,%3}, {%4,%5,%6,%7}, {%8,%9}, {%0,%1,%2,%3};"
        : "+f"(c[0]), "+f"(c[1]), "+f"(c[2]), "+f"(c[3])
        : "r"(a0), "r"(a1), "r"(a2), "r"(a3), "r"(b0), "r"(b1));
}
__device__ __forceinline__ uint32_t fu(float v) { return __float_as_uint(v); }
__device__ __forceinline__ bool mask_at(const void* m, int idx, int u8) {
    if (u8) return ((const unsigned char*)m)[idx] != 0;
    return ((const int*)m)[idx] != 0;
}

// ---------------- count (with fused u8/i32 layout detection) ----------------
__global__ __launch_bounds__(256) void count_kernel(const void* __restrict__ mask) {
    const int b = blockIdx.x, tid = threadIdx.x;
    __shared__ int found;
    if (tid == 0) found = 0;
    __syncthreads();
    {
        const unsigned char* mb = (const unsigned char*)mask;
        int local = 0;
        for (int i = tid; i < 4096; i += 256)
            if ((i & 3) && mb[i]) local = 1;
        if (local) atomicOr(&found, 1);
    }
    __syncthreads();
    const int u8 = found;

    __shared__ int cnt[256];
    __shared__ int excl[257];
    int loc[16], c = 0;
#pragma unroll
    for (int t = 0; t < 16; t++) {
        const int l = tid * 16 + t;
        loc[t] = mask_at(mask, b * Ln + l, u8) ? 0 : 1;
        c += loc[t];
    }
    cnt[tid] = c;
    __syncthreads();
    if (tid == 0) {
        int s = 0;
        for (int i = 0; i < 256; i++) { excl[i] = s; s += cnt[i]; }
        excl[256] = s;
        g_Lc[b] = s;
        g_Lcp256[b] = (s + 255) & ~255;
        g_Lcp128[b] = (s + 127) & ~127;
    }
    __syncthreads();
    int j = excl[tid];
#pragma unroll
    for (int t = 0; t < 16; t++) {
        const int l = tid * 16 + t;
        if (loc[t]) { g_idx[b][j] = l; g_rank[b][l] = j; j++; }
        else g_rank[b][l] = -1;
    }
}

// ---------------- prep: rounded w; compacted+rounded x (zero pad) ----------------
__global__ __launch_bounds__(256) void prep_w(const float4* __restrict__ w) {
    const int r = blockIdx.x, tid = threadIdx.x;
    float4 v = w[(size_t)r * 256 + tid];
    v.x = tf32r(v.x); v.y = tf32r(v.y); v.z = tf32r(v.z); v.w = tf32r(v.w);
    ((float4*)g_w32)[(size_t)r * 256 + tid] = v;
}

__global__ __launch_bounds__(256) void prep_x(const float4* __restrict__ x) {
    const int b = blockIdx.y, j = blockIdx.x, tid = threadIdx.x;
    if (j >= g_Lcp256[b]) return;
    float4* dst = (float4*)g_x32 + ((size_t)b * Ln + j) * 256;
    if (j >= g_Lc[b]) { dst[tid] = make_float4(0.f, 0.f, 0.f, 0.f); return; }
    const int l = g_idx[b][j];
    float4 v = x[((size_t)b * Ln + l) * 256 + tid];
    v.x = tf32r(v.x); v.y = tf32r(v.y); v.z = tf32r(v.z); v.w = tf32r(v.w);
    dst[tid] = v;
}

// ---------------- WqT: g_qT[0..Dn*Dn) = transpose of g_w32 rows 0..1023 ----------------
__global__ __launch_bounds__(256) void wq_transpose() {
    __shared__ float t[32][33];
    const int c0 = blockIdx.x * 32, d0 = blockIdx.y * 32;
    const int tx = threadIdx.x & 31, ty = threadIdx.x >> 5;
#pragma unroll
    for (int k = 0; k < 4; k++)
        t[ty + 8 * k][tx] = g_w32[(size_t)(c0 + ty + 8 * k) * Dn + d0 + tx];
    __syncthreads();
#pragma unroll
    for (int k = 0; k < 4; k++)
        g_qT[(size_t)(d0 + ty + 8 * k) * Dn + c0 + tx] = t[tx][ty + 8 * k];
}

// ---------------- GEMM: C(M x N) = A(M x K) @ B(N x K)^T ----------------
// Tiles 128x256x32, 512 threads (16 warps, warp tile 64x32), 3-stage pipeline,
// k-interleaved LDS.64, row stride 40 (conflict-free).
// MODE 0: n-limited by Lcp256 (GEMM1 k,v), tf32-round output.
// MODE 1: m-limited by Lcp128 (GEMM2), bias + scatter rows via g_idx (final out).
// MODE 2: no guard (M-gemm), output = tf32r(0.125 * acc).
#define RS 40
#define STGF ((128 + 256) * RS)
#define NST 3
#define SMG (NST * STGF * 4)       // 184320 B

template <int MODE>
__global__ __launch_bounds__(512, 1) void gemm_tc(
    const float* __restrict__ Aall, const float* __restrict__ Ball,
    float* __restrict__ Call, const float* __restrict__ bias,
    int K, int ldc, size_t bsA, size_t bsB, size_t bsC) {
    const int b = blockIdx.z;
    const int m0 = blockIdx.x * 128, n0 = blockIdx.y * 256;
    if (MODE == 0) { if (n0 >= g_Lcp256[b]) return; }
    if (MODE == 1) { if (m0 >= g_Lcp128[b]) return; }

    extern __shared__ float sm[];
    const uint32_t smb = smem_u32(sm);
    const int tid = threadIdx.x, lane = tid & 31, wid = tid >> 5;
    const float* A = Aall + bsA * b;
    const float* Bp = Ball + bsB * b;
    float* C = Call + bsC * b;

    const int g = lane >> 2, t4 = lane & 3;
    const int warpM = wid & 1, warpN = wid >> 1;      // 2 x 8 warps
    const int mrow0 = warpM * 64, ncol0 = warpN * 32;

    float acc[4][4][4];
#pragma unroll
    for (int mf = 0; mf < 4; mf++)
#pragma unroll
        for (int nf = 0; nf < 4; nf++)
#pragma unroll
            for (int j = 0; j < 4; j++) acc[mf][nf][j] = 0.f;

    auto load_stage = [&](int s, int ko) {
        const uint32_t sb = smb + (uint32_t)(s * STGF) * 4;
        {   // A: 128 rows x 32 k, 4 threads/row
            const int row = tid >> 2, c2 = (tid & 3) * 8;
            const float* src = A + (size_t)(m0 + row) * K + ko + c2;
            const uint32_t dst = sb + (uint32_t)(row * RS + c2) * 4;
            cpasync16(dst, src);
            cpasync16(dst + 16, src + 4);
        }
        {   // B: 256 rows x 32 k, 2 threads/row
            const int row = tid & 255, kh = (tid >> 8) * 16;
            const float* src = Bp + (size_t)(n0 + row) * K + ko + kh;
            const uint32_t dst = sb + (uint32_t)((128 + row) * RS + kh) * 4;
#pragma unroll
            for (int j = 0; j < 4; j++) cpasync16(dst + j * 16, src + j * 4);
        }
    };

    const int NIT = K >> 5;
    load_stage(0, 0);  CP_COMMIT();
    load_stage(1, 32); CP_COMMIT();

    for (int i = 0; i < NIT; i++) {
        CP_WAIT1();
        __syncthreads();
        if (i + 2 < NIT) load_stage((i + 2) % NST, (i + 2) * 32);
        CP_COMMIT();

        const float* As = sm + (i % NST) * STGF;
        const float* Bs = As + 128 * RS;
#pragma unroll
        for (int kk = 0; kk < 32; kk += 8) {
            float2 alo[4], ahi[4];
#pragma unroll
            for (int mf = 0; mf < 4; mf++) {
                const float* ap = As + (mrow0 + mf * 16 + g) * RS + kk + 2 * t4;
                alo[mf] = *(const float2*)ap;
                ahi[mf] = *(const float2*)(ap + 8 * RS);
            }
#pragma unroll
            for (int nf = 0; nf < 4; nf++) {
                const float2 bv = *(const float2*)(Bs + (ncol0 + nf * 8 + g) * RS + kk + 2 * t4);
                const uint32_t b0 = fu(bv.x), b1 = fu(bv.y);
#pragma unroll
                for (int mf = 0; mf < 4; mf++)
                    mma8(acc[mf][nf], fu(alo[mf].x), fu(ahi[mf].x), fu(alo[mf].y), fu(ahi[mf].y), b0, b1);
            }
        }
    }

    if (MODE == 0 || MODE == 2) {
        const float sc = (MODE == 2) ? 0.125f : 1.0f;
#pragma unroll
        for (int mf = 0; mf < 4; mf++) {
            const int r0 = m0 + mrow0 + mf * 16 + g;
#pragma unroll
            for (int nf = 0; nf < 4; nf++) {
                const int c0 = n0 + ncol0 + nf * 8 + 2 * t4;
                float2 v0 = make_float2(tf32r(sc * acc[mf][nf][0]), tf32r(sc * acc[mf][nf][1]));
                float2 v1 = make_float2(tf32r(sc * acc[mf][nf][2]), tf32r(sc * acc[mf][nf][3]));
                *(float2*)(C + (size_t)r0 * ldc + c0) = v0;
                *(float2*)(C + (size_t)(r0 + 8) * ldc + c0) = v1;
            }
        }
    } else {
        const int lc = g_Lc[b];
#pragma unroll
        for (int mf = 0; mf < 4; mf++) {
            const int r0 = m0 + mrow0 + mf * 16 + g;
            const int la = (r0 < lc) ? g_idx[b][r0] : -1;
            const int lb2 = (r0 + 8 < lc) ? g_idx[b][r0 + 8] : -1;
#pragma unroll
            for (int nf = 0; nf < 4; nf++) {
                const int c0 = n0 + ncol0 + nf * 8 + 2 * t4;
                const float2 bb = *(const float2*)(bias + c0);
                if (la >= 0) {
                    float2 v0 = make_float2(acc[mf][nf][0] + bb.x, acc[mf][nf][1] + bb.y);
                    *(float2*)(C + (size_t)la * ldc + c0) = v0;
                }
                if (lb2 >= 0) {
                    float2 v1 = make_float2(acc[mf][nf][2] + bb.x, acc[mf][nf][3] + bb.y);
                    *(float2*)(C + (size_t)lb2 * ldc + c0) = v1;
                }
            }
        }
    }
}

// ---------------- fill masked rows of out with bias ----------------
__global__ __launch_bounds__(256) void fill_bias(const float4* __restrict__ bout,
                                                 float4* __restrict__ out) {
    const int b = blockIdx.y, l = blockIdx.x, tid = threadIdx.x;
    if (g_rank[b][l] >= 0) return;
    out[((size_t)b * Ln + l) * 256 + tid] = bout[tid];
}

// ---------------- softmax on k rows over compact cols; zeroes g_ctx + pad ----------------
__global__ __launch_bounds__(256) void softmax_kernel() {
    const int b = blockIdx.y, r = blockIdx.x;
    const int tid = threadIdx.x;
    {
        const int gid = ((blockIdx.y * 1024 + blockIdx.x) << 8) + tid;
        if (gid < Bn * Hn * 64 * 64) g_ctx[gid] = 0.f;
    }
    const int lc = g_Lc[b], lcp = g_Lcp256[b];
    float* rowp = g_qkv + (size_t)b * O3 * Ln + (size_t)(1024 + r) * Ln;
    float sum = 0.f;
    for (int l = tid; l < lc; l += 256) sum += expf(rowp[l]);
    __shared__ float red[256];
    red[tid] = sum;
    __syncthreads();
    for (int s = 128; s > 0; s >>= 1) {
        if (tid < s) red[tid] += red[tid + s];
        __syncthreads();
    }
    const float inv = 1.f / red[0];
    for (int l = tid; l < lcp; l += 256)
        rowp[l] = (l < lc) ? tf32r(expf(rowp[l]) * inv) : 0.f;
}

// ---------------- context: chunks of 256 compact cols, 128x128, 2-stage (R9 verbatim) ----------------
#define CSTGF (2 * 128 * RS)
#define SMC (2 * CSTGF * 4)   // 81920 B

__global__ __launch_bounds__(256, 2) void ctx_tc() {
    const int b = blockIdx.z, hp = blockIdx.x, ch = blockIdx.y;
    const int l0 = ch * 256;
    if (l0 >= g_Lcp256[b]) return;

    extern __shared__ float sm[];
    const uint32_t smb = smem_u32(sm);
    const int tid = threadIdx.x, lane = tid & 31, wid = tid >> 5;
    const float* A = g_qkv + (size_t)b * O3 * Ln + (size_t)(1024 + hp * 128) * Ln + l0;
    const float* Bp = g_qkv + (size_t)b * O3 * Ln + (size_t)(2048 + hp * 128) * Ln + l0;

    const int g = lane >> 2, t4 = lane & 3;
    const int warpM = wid & 1, warpN = wid >> 1;
    const int mrow0 = warpM * 64, ncol0 = warpN * 32;

    float acc[4][4][4];
#pragma unroll
    for (int mf = 0; mf < 4; mf++)
#pragma unroll
        for (int nf = 0; nf < 4; nf++)
#pragma unroll
            for (int j = 0; j < 4; j++) acc[mf][nf][j] = 0.f;

    auto load_stage = [&](int s, int ko) {
        const uint32_t sb = smb + (uint32_t)(s * CSTGF) * 4;
        const int row = tid >> 1, kh = (tid & 1) * 16;
        const float* srcA = A + (size_t)row * Ln + ko + kh;
        const float* srcB = Bp + (size_t)row * Ln + ko + kh;
        const uint32_t dA = sb + (uint32_t)(row * RS + kh) * 4;
        const uint32_t dB = sb + (uint32_t)((128 + row) * RS + kh) * 4;
#pragma unroll
        for (int j = 0; j < 4; j++) {
            cpasync16(dA + j * 16, srcA + j * 4);
            cpasync16(dB + j * 16, srcB + j * 4);
        }
    };

    const int NIT = 8;
    load_stage(0, 0);
    CP_COMMIT();

    for (int i = 0; i < NIT; i++) {
        if (i + 1 < NIT) { load_stage((i + 1) & 1, (i + 1) * 32); CP_COMMIT(); CP_WAIT1(); }
        else             { CP_WAIT0(); }
        __syncthreads();

        const float* As = sm + (i & 1) * CSTGF;
        const float* Bs = As + 128 * RS;
#pragma unroll
        for (int kk = 0; kk < 32; kk += 8) {
            float2 alo[4], ahi[4];
#pragma unroll
            for (int mf = 0; mf < 4; mf++) {
                const float* ap = As + (mrow0 + mf * 16 + g) * RS + kk + 2 * t4;
                alo[mf] = *(const float2*)ap;
                ahi[mf] = *(const float2*)(ap + 8 * RS);
            }
#pragma unroll
            for (int nf = 0; nf < 4; nf++) {
                const float2 bv = *(const float2*)(Bs + (ncol0 + nf * 8 + g) * RS + kk + 2 * t4);
                const uint32_t b0 = fu(bv.x), b1 = fu(bv.y);
#pragma unroll
                for (int mf = 0; mf < 4; mf++)
                    mma8(acc[mf][nf], fu(alo[mf].x), fu(ahi[mf].x), fu(alo[mf].y), fu(ahi[mf].y), b0, b1);
            }
        }
        __syncthreads();
    }

    if (warpM == (warpN >> 1)) {
        const int h = hp * 2 + warpM;
        float* cp = g_ctx + (size_t)(b * Hn + h) * 64 * 64;
#pragma unroll
        for (int mf = 0; mf < 4; mf++) {
            const int d0 = mf * 16 + g;
#pragma unroll
            for (int nf = 0; nf < 4; nf++) {
                const int e0 = (warpN & 1) * 32 + nf * 8 + 2 * t4;
                atomicAdd(cp + (size_t)d0 * 64 + e0, acc[mf][nf][0]);
                atomicAdd(cp + (size_t)d0 * 64 + e0 + 1, acc[mf][nf][1]);
                atomicAdd(cp + (size_t)(d0 + 8) * 64 + e0, acc[mf][nf][2]);
                atomicAdd(cp + (size_t)(d0 + 8) * 64 + e0 + 1, acc[mf][nf][3]);
            }
        }
    }
}

// ---------------- weff (SIMT, f32 in, tf32 out) ----------------
__global__ __launch_bounds__(256) void weff_kernel(const float* __restrict__ wout) {
    __shared__ float Ws[64][65];
    __shared__ float Cs[64][68];
    const int b = blockIdx.z, h = blockIdx.y, o0 = blockIdx.x * 64;
    const int tid = threadIdx.x;
    const int rr = tid >> 2;
    const int q4 = (tid & 3) * 16;
    const float* wp = wout + (size_t)(o0 + rr) * Dn + h * 64 + q4;
#pragma unroll
    for (int j = 0; j < 16; j += 4) {
        float4 t4v = *(const float4*)(wp + j);
        Ws[q4 + j + 0][rr] = t4v.x; Ws[q4 + j + 1][rr] = t4v.y;
        Ws[q4 + j + 2][rr] = t4v.z; Ws[q4 + j + 3][rr] = t4v.w;
    }
    const float* cp = g_ctx + ((size_t)(b * Hn + h) * 64 + rr) * 64 + q4;
#pragma unroll
    for (int j = 0; j < 16; j += 4) *(float4*)&Cs[rr][q4 + j] = *(const float4*)(cp + j);
    __syncthreads();

    const int oo = tid >> 2, eg = tid & 3;
    float acc[16];
#pragma unroll
    for (int j = 0; j < 16; j++) acc[j] = 0.f;
#pragma unroll 8
    for (int dd = 0; dd < 64; dd++) {
        const float wv = Ws[dd][oo];
#pragma unroll
        for (int j = 0; j < 16; j++) acc[j] = fmaf(wv, Cs[dd][eg * 16 + j], acc[j]);
    }
    float* op = g_weff + (size_t)b * Dn * Dn + (size_t)(o0 + oo) * Dn + h * 64 + eg * 16;
#pragma unroll
    for (int j = 0; j < 16; j += 4)
        *(float4*)(op + j) = make_float4(tf32r(acc[j]), tf32r(acc[j + 1]),
                                         tf32r(acc[j + 2]), tf32r(acc[j + 3]));
}

// ---------------- host side ----------------
extern "C" void kernel_launch(void* const* d_in, const int* in_sizes, int n_in,
                              void* d_out, int out_size) {
    const float* x = (const float*)d_in[0];
    const void* masks = d_in[1];
    const float* w_qkv = (const float*)d_in[2];
    const float* w_out = (const float*)d_in[3];
    const float* b_out = (const float*)d_in[4];
    float* out = (float*)d_out;

    void *pQ, *pQT, *pWE, *pX, *pW;
    cudaGetSymbolAddress(&pQ, g_qkv);
    cudaGetSymbolAddress(&pQT, g_qT);
    cudaGetSymbolAddress(&pWE, g_weff);
    cudaGetSymbolAddress(&pX, g_x32);
    cudaGetSymbolAddress(&pW, g_w32);

    float* wqT = (float*)pQT;                          // Dn x Dn
    float* M   = (float*)pQT + (size_t)Dn * Dn;        // Bn x Dn x Dn

    cudaFuncSetAttribute(gemm_tc<0>, cudaFuncAttributeMaxDynamicSharedMemorySize, SMG);
    cudaFuncSetAttribute(gemm_tc<1>, cudaFuncAttributeMaxDynamicSharedMemorySize, SMG);
    cudaFuncSetAttribute(gemm_tc<2>, cudaFuncAttributeMaxDynamicSharedMemorySize, SMG);
    cudaFuncSetAttribute(ctx_tc, cudaFuncAttributeMaxDynamicSharedMemorySize, SMC);

    count_kernel<<<Bn, 256>>>(masks);                    // launch 1
    prep_w<<<O3, 256>>>((const float4*)w_qkv);           // launch 2
    prep_x<<<dim3(Ln, Bn), 256>>>((const float4*)x);     // launch 3

    // GEMM1 (launch 4 -> ncu target): k,v rows only:
    // g_qkv rows [1024,3072) = g_w32 rows [1024,3072) @ g_x32[b]^T
    gemm_tc<0><<<dim3(16, 16, Bn), 512, SMG>>>(
        (const float*)pW + (size_t)1024 * Dn, (const float*)pX,
        (float*)pQ + (size_t)1024 * Ln, nullptr,
        Dn, Ln, (size_t)0, (size_t)Ln * Dn, (size_t)O3 * Ln);

    fill_bias<<<dim3(Ln, Bn), 256>>>((const float4*)b_out, (float4*)out);

    wq_transpose<<<dim3(32, 32), 256>>>();

    softmax_kernel<<<dim3(1024, Bn), 256>>>();

    ctx_tc<<<dim3(8, 16, Bn), 256, SMC>>>();

    weff_kernel<<<dim3(16, Hn, Bn), 256>>>(w_out);

    // M[b] = 0.125 * Weff[b] @ WqT^T   (A=(o,c), B=(d,c) -> C=(o,d))
    gemm_tc<2><<<dim3(8, 4, Bn), 512, SMG>>>(
        (const float*)pWE, wqT, M, nullptr,
        Dn, Dn, (size_t)Dn * Dn, (size_t)0, (size_t)Dn * Dn);

    // GEMM2: out rows (scattered via g_idx) = g_x32[b] @ M[b]^T + b_out
    gemm_tc<1><<<dim3(32, 4, Bn), 512, SMG>>>(
        (const float*)pX, M, out, b_out,
        Dn, Dn, (size_t)Ln * Dn, (size_t)Dn * Dn, (size_t)Ln * Dn);
}

// round 13
// speedup vs baseline: 2.8761x; 1.6477x over previous
#include <cuda_runtime.h>
#include <cuda_fp16.h>
#include <math.h>
#include <cstdint>

#define Bn 8
#define Ln 4096
#define Dn 1024
#define Hn 16

// ---------------- scratch (static device globals; no allocation) ----------------
__device__ __align__(256) __half g_x16[(size_t)Bn * Ln * Dn];     // compacted+rounded x (fp16)
__device__ __align__(256) __half g_kv16[(size_t)Bn * 2048 * Ln];  // k rows [0,1024), v rows [1024,2048)
__device__ __align__(256) __half g_wkv16[(size_t)2048 * Dn];      // w_qkv rows 1024..3071 (fp16)
__device__ __align__(256) __half g_wqT16[(size_t)Dn * Dn];        // Wq^T (d,c) fp16
__device__ __align__(256) __half g_weff16[(size_t)Bn * Dn * Dn];  // Weff fp16
__device__ __align__(256) __half g_M16[(size_t)Bn * Dn * Dn];     // M = 0.125*Weff@Wq fp16
__device__ __align__(256) float  g_ctx[Bn * Hn * 64 * 64];        // f32 accumulator (x256 scaled)
__device__ int g_idx[Bn][Ln];
__device__ int g_rank[Bn][Ln];
__device__ int g_Lc[Bn];
__device__ int g_Lcp256[Bn];
__device__ int g_Lcp128[Bn];

// ---------------- helpers ----------------
__device__ __forceinline__ uint32_t smem_u32(const void* p) {
    uint32_t a;
    asm("{ .reg .u64 t; cvta.to.shared.u64 t, %1; cvt.u32.u64 %0, t; }" : "=r"(a) : "l"(p));
    return a;
}
__device__ __forceinline__ void cpasync16(uint32_t dst, const void* src) {
    asm volatile("cp.async.cg.shared.global [%0], [%1], 16;" :: "r"(dst), "l"(src) : "memory");
}
#define CP_COMMIT() asm volatile("cp.async.commit_group;" ::: "memory")
#define CP_WAIT1()  asm volatile("cp.async.wait_group 1;" ::: "memory")
#define CP_WAIT0()  asm volatile("cp.async.wait_group 0;" ::: "memory")

__device__ __forceinline__ void mma16(float* c, uint32_t a0, uint32_t a1, uint32_t a2, uint32_t a3,
                                      uint32_t b0, uint32_t b1) {
    asm volatile("mma.sync.aligned.m16n8k16.row.col.f32.f16.f16.f32 "
        "{%0,%1,%2,%3}, {%4,%5,%6,%7}, {%8,%9}, {%0,%1,%2,%3};"
        : "+f"(c[0]), "+f"(c[1]), "+f"(c[2]), "+f"(c[3])
        : "r"(a0), "r"(a1), "r"(a2), "r"(a3), "r"(b0), "r"(b1));
}
__device__ __forceinline__ bool mask_at(const void* m, int idx, int u8) {
    if (u8) return ((const unsigned char*)m)[idx] != 0;
    return ((const int*)m)[idx] != 0;
}

// ---------------- count (with fused u8/i32 layout detection) ----------------
__global__ __launch_bounds__(256) void count_kernel(const void* __restrict__ mask) {
    const int b = blockIdx.x, tid = threadIdx.x;
    __shared__ int found;
    if (tid == 0) found = 0;
    __syncthreads();
    {
        const unsigned char* mb = (const unsigned char*)mask;
        int local = 0;
        for (int i = tid; i < 4096; i += 256)
            if ((i & 3) && mb[i]) local = 1;
        if (local) atomicOr(&found, 1);
    }
    __syncthreads();
    const int u8 = found;

    __shared__ int cnt[256];
    __shared__ int excl[257];
    int loc[16], c = 0;
#pragma unroll
    for (int t = 0; t < 16; t++) {
        const int l = tid * 16 + t;
        loc[t] = mask_at(mask, b * Ln + l, u8) ? 0 : 1;
        c += loc[t];
    }
    cnt[tid] = c;
    __syncthreads();
    if (tid == 0) {
        int s = 0;
        for (int i = 0; i < 256; i++) { excl[i] = s; s += cnt[i]; }
        excl[256] = s;
        g_Lc[b] = s;
        g_Lcp256[b] = (s + 255) & ~255;
        g_Lcp128[b] = (s + 127) & ~127;
    }
    __syncthreads();
    int j = excl[tid];
#pragma unroll
    for (int t = 0; t < 16; t++) {
        const int l = tid * 16 + t;
        if (loc[t]) { g_idx[b][j] = l; g_rank[b][l] = j; j++; }
        else g_rank[b][l] = -1;
    }
}

// ---------------- prep: w_kv rows -> fp16; compacted x -> fp16 (zero pad) ----------------
__global__ __launch_bounds__(256) void prep_w16(const float4* __restrict__ w) {
    const int r = blockIdx.x, tid = threadIdx.x;       // r in [0,2048)
    float4 v = w[((size_t)(1024 + r) * Dn + tid * 4) >> 2];
    __half* p = g_wkv16 + (size_t)r * Dn + tid * 4;
    *(__half2*)p = __floats2half2_rn(v.x, v.y);
    *(__half2*)(p + 2) = __floats2half2_rn(v.z, v.w);
}

__global__ __launch_bounds__(256) void prep_x16(const float4* __restrict__ x) {
    const int b = blockIdx.y, j = blockIdx.x, tid = threadIdx.x;
    if (j >= g_Lcp256[b]) return;
    __half* dst = g_x16 + ((size_t)b * Ln + j) * Dn + tid * 4;
    if (j >= g_Lc[b]) {
        *(__half2*)dst = __floats2half2_rn(0.f, 0.f);
        *(__half2*)(dst + 2) = __floats2half2_rn(0.f, 0.f);
        return;
    }
    const int l = g_idx[b][j];
    float4 v = x[((size_t)b * Ln + l) * 256 + tid];
    *(__half2*)dst = __floats2half2_rn(v.x, v.y);
    *(__half2*)(dst + 2) = __floats2half2_rn(v.z, v.w);
}

// ---------------- WqT16: (d,c) = transpose of w_qkv rows 0..1023, fp16 ----------------
__global__ __launch_bounds__(256) void wq_t16(const float* __restrict__ w) {
    __shared__ float t[32][33];
    const int c0 = blockIdx.x * 32, d0 = blockIdx.y * 32;
    const int tx = threadIdx.x & 31, ty = threadIdx.x >> 5;
#pragma unroll
    for (int k = 0; k < 4; k++)
        t[ty + 8 * k][tx] = w[(size_t)(c0 + ty + 8 * k) * Dn + d0 + tx];
    __syncthreads();
#pragma unroll
    for (int k = 0; k < 4; k++)
        g_wqT16[(size_t)(d0 + ty + 8 * k) * Dn + c0 + tx] = __float2half_rn(t[tx][ty + 8 * k]);
}

// ---------------- fp16 GEMM: C(M x N) = A(M x K) @ B(N x K)^T ----------------
// Tiles 128x256x64, 512 threads (16 warps, warp tile 64x32), 3-stage pipeline,
// m16n8k16 with contiguous-4 k-interleave (LDS.64), row stride 80 halfs (conflict-free).
// MODE 0: n-guard Lcp256, fp16 out (GEMM1 k,v).
// MODE 1: m-guard Lcp128, f32 out + bias + row scatter via g_idx (final out).
// MODE 2: no guard, fp16 out * 0.125 (M-gemm).
#define RH 80
#define STH ((128 + 256) * RH)    // 30720 halfs / stage
#define NSTH 3
#define SMH (NSTH * STH * 2)      // 184320 B

template <int MODE>
__global__ __launch_bounds__(512, 1) void gemm16(
    const __half* __restrict__ Aall, const __half* __restrict__ Ball,
    void* __restrict__ Call, const float* __restrict__ bias,
    int K, int ldc, size_t bsA, size_t bsB, size_t bsC) {
    const int b = blockIdx.z;
    const int m0 = blockIdx.x * 128, n0 = blockIdx.y * 256;
    if (MODE == 0) { if (n0 >= g_Lcp256[b]) return; }
    if (MODE == 1) { if (m0 >= g_Lcp128[b]) return; }

    extern __shared__ __half smh[];
    const uint32_t smb = smem_u32(smh);
    const int tid = threadIdx.x, lane = tid & 31, wid = tid >> 5;
    const __half* A = Aall + bsA * b;
    const __half* Bp = Ball + bsB * b;

    const int g = lane >> 2, t4 = lane & 3;
    const int warpM = wid & 1, warpN = wid >> 1;      // 2 x 8 warps
    const int mrow0 = warpM * 64, ncol0 = warpN * 32;

    float acc[4][4][4];
#pragma unroll
    for (int mf = 0; mf < 4; mf++)
#pragma unroll
        for (int nf = 0; nf < 4; nf++)
#pragma unroll
            for (int j = 0; j < 4; j++) acc[mf][nf][j] = 0.f;

    auto load_stage = [&](int s, int ko) {
        const uint32_t sb = smb + (uint32_t)(s * STH) * 2;
        {   // A: 128 rows x 64 halfs, 4 threads/row, 32B each
            const int row = tid >> 2, ch = (tid & 3) * 16;
            const __half* src = A + (size_t)(m0 + row) * K + ko + ch;
            const uint32_t dst = sb + (uint32_t)(row * RH + ch) * 2;
            cpasync16(dst, src);
            cpasync16(dst + 16, src + 8);
        }
        {   // B: 256 rows x 64 halfs, 2 threads/row, 64B each
            const int row = tid & 255, kh = (tid >> 8) * 32;
            const __half* src = Bp + (size_t)(n0 + row) * K + ko + kh;
            const uint32_t dst = sb + (uint32_t)((128 + row) * RH + kh) * 2;
#pragma unroll
            for (int j = 0; j < 4; j++) cpasync16(dst + j * 16, src + j * 8);
        }
    };

    const int NIT = K >> 6;
    load_stage(0, 0);  CP_COMMIT();
    load_stage(1, 64); CP_COMMIT();

    for (int i = 0; i < NIT; i++) {
        CP_WAIT1();
        __syncthreads();
        if (i + 2 < NIT) load_stage((i + 2) % NSTH, (i + 2) * 64);
        CP_COMMIT();

        const __half* As = smh + (i % NSTH) * STH;
        const __half* Bs = As + 128 * RH;
#pragma unroll
        for (int ks = 0; ks < 64; ks += 16) {
            uint2 aLo[4], aHi[4];
#pragma unroll
            for (int mf = 0; mf < 4; mf++) {
                const __half* ap = As + (mrow0 + mf * 16 + g) * RH + ks + 4 * t4;
                aLo[mf] = *(const uint2*)ap;
                aHi[mf] = *(const uint2*)(ap + 8 * RH);
            }
#pragma unroll
            for (int nf = 0; nf < 4; nf++) {
                const uint2 bv = *(const uint2*)(Bs + (ncol0 + nf * 8 + g) * RH + ks + 4 * t4);
#pragma unroll
                for (int mf = 0; mf < 4; mf++)
                    mma16(acc[mf][nf], aLo[mf].x, aHi[mf].x, aLo[mf].y, aHi[mf].y, bv.x, bv.y);
            }
        }
    }

    if (MODE == 0 || MODE == 2) {
        __half* Ch = (__half*)Call + bsC * b;
        const float sc = (MODE == 2) ? 0.125f : 1.0f;
#pragma unroll
        for (int mf = 0; mf < 4; mf++) {
            const int r0 = m0 + mrow0 + mf * 16 + g;
#pragma unroll
            for (int nf = 0; nf < 4; nf++) {
                const int c0 = n0 + ncol0 + nf * 8 + 2 * t4;
                *(__half2*)(Ch + (size_t)r0 * ldc + c0) =
                    __floats2half2_rn(sc * acc[mf][nf][0], sc * acc[mf][nf][1]);
                *(__half2*)(Ch + (size_t)(r0 + 8) * ldc + c0) =
                    __floats2half2_rn(sc * acc[mf][nf][2], sc * acc[mf][nf][3]);
            }
        }
    } else {
        float* C = (float*)Call + bsC * b;
        const int lc = g_Lc[b];
#pragma unroll
        for (int mf = 0; mf < 4; mf++) {
            const int r0 = m0 + mrow0 + mf * 16 + g;
            const int la = (r0 < lc) ? g_idx[b][r0] : -1;
            const int lb2 = (r0 + 8 < lc) ? g_idx[b][r0 + 8] : -1;
#pragma unroll
            for (int nf = 0; nf < 4; nf++) {
                const int c0 = n0 + ncol0 + nf * 8 + 2 * t4;
                const float2 bb = *(const float2*)(bias + c0);
                if (la >= 0)
                    *(float2*)(C + (size_t)la * ldc + c0) =
                        make_float2(acc[mf][nf][0] + bb.x, acc[mf][nf][1] + bb.y);
                if (lb2 >= 0)
                    *(float2*)(C + (size_t)lb2 * ldc + c0) =
                        make_float2(acc[mf][nf][2] + bb.x, acc[mf][nf][3] + bb.y);
            }
        }
    }
}

// ---------------- fill masked rows of out with bias ----------------
__global__ __launch_bounds__(256) void fill_bias(const float4* __restrict__ bout,
                                                 float4* __restrict__ out) {
    const int b = blockIdx.y, l = blockIdx.x, tid = threadIdx.x;
    if (g_rank[b][l] >= 0) return;
    out[((size_t)b * Ln + l) * 256 + tid] = bout[tid];
}

// ---------------- softmax on k rows (fp16 in/out, x256 scale); zeroes g_ctx ----------------
__global__ __launch_bounds__(256) void softmax_kernel() {
    const int b = blockIdx.y, r = blockIdx.x;
    const int tid = threadIdx.x;
    {
        const int gid = ((blockIdx.y * 1024 + blockIdx.x) << 8) + tid;
        if (gid < Bn * Hn * 64 * 64) g_ctx[gid] = 0.f;
    }
    const int lc = g_Lc[b], lcp = g_Lcp256[b];
    __half* rowp = g_kv16 + (size_t)b * 2048 * Ln + (size_t)r * Ln;
    float sum = 0.f;
    for (int l = tid; l < lc; l += 256) sum += expf(__half2float(rowp[l]));
    __shared__ float red[256];
    red[tid] = sum;
    __syncthreads();
    for (int s = 128; s > 0; s >>= 1) {
        if (tid < s) red[tid] += red[tid + s];
        __syncthreads();
    }
    const float inv = 256.f / red[0];   // x256: keeps k_sm in fp16 normal range
    for (int l = tid; l < lcp; l += 256)
        rowp[l] = (l < lc) ? __float2half_rn(expf(__half2float(rowp[l])) * inv)
                           : __float2half_rn(0.f);
}

// ---------------- context fp16: 128x128 tiles over 256-col chunks, k-chunk 64 ----------------
#define CSTH (2 * 128 * RH)      // 20480 halfs / stage
#define SMC2 (2 * CSTH * 2)      // 81920 B

__global__ __launch_bounds__(256, 2) void ctx16() {
    const int b = blockIdx.z, hp = blockIdx.x, ch = blockIdx.y;
    const int l0 = ch * 256;
    if (l0 >= g_Lcp256[b]) return;

    extern __shared__ __half smh[];
    const uint32_t smb = smem_u32(smh);
    const int tid = threadIdx.x, lane = tid & 31, wid = tid >> 5;
    const __half* A = g_kv16 + (size_t)b * 2048 * Ln + (size_t)(hp * 128) * Ln + l0;          // k_sm
    const __half* Bp = g_kv16 + (size_t)b * 2048 * Ln + (size_t)(1024 + hp * 128) * Ln + l0;  // v

    const int g = lane >> 2, t4 = lane & 3;
    const int warpM = wid & 1, warpN = wid >> 1;
    const int mrow0 = warpM * 64, ncol0 = warpN * 32;

    float acc[4][4][4];
#pragma unroll
    for (int mf = 0; mf < 4; mf++)
#pragma unroll
        for (int nf = 0; nf < 4; nf++)
#pragma unroll
            for (int j = 0; j < 4; j++) acc[mf][nf][j] = 0.f;

    auto load_stage = [&](int s, int ko) {
        const uint32_t sb = smb + (uint32_t)(s * CSTH) * 2;
        const int row = tid >> 1, kh = (tid & 1) * 32;
        const __half* srcA = A + (size_t)row * Ln + ko + kh;
        const __half* srcB = Bp + (size_t)row * Ln + ko + kh;
        const uint32_t dA = sb + (uint32_t)(row * RH + kh) * 2;
        const uint32_t dB = sb + (uint32_t)((128 + row) * RH + kh) * 2;
#pragma unroll
        for (int j = 0; j < 4; j++) {
            cpasync16(dA + j * 16, srcA + j * 8);
            cpasync16(dB + j * 16, srcB + j * 8);
        }
    };

    const int NIT = 4;   // 256 / 64
    load_stage(0, 0);
    CP_COMMIT();

    for (int i = 0; i < NIT; i++) {
        if (i + 1 < NIT) { load_stage((i + 1) & 1, (i + 1) * 64); CP_COMMIT(); CP_WAIT1(); }
        else             { CP_WAIT0(); }
        __syncthreads();

        const __half* As = smh + (i & 1) * CSTH;
        const __half* Bs = As + 128 * RH;
#pragma unroll
        for (int ks = 0; ks < 64; ks += 16) {
            uint2 aLo[4], aHi[4];
#pragma unroll
            for (int mf = 0; mf < 4; mf++) {
                const __half* ap = As + (mrow0 + mf * 16 + g) * RH + ks + 4 * t4;
                aLo[mf] = *(const uint2*)ap;
                aHi[mf] = *(const uint2*)(ap + 8 * RH);
            }
#pragma unroll
            for (int nf = 0; nf < 4; nf++) {
                const uint2 bv = *(const uint2*)(Bs + (ncol0 + nf * 8 + g) * RH + ks + 4 * t4);
#pragma unroll
                for (int mf = 0; mf < 4; mf++)
                    mma16(acc[mf][nf], aLo[mf].x, aHi[mf].x, aLo[mf].y, aHi[mf].y, bv.x, bv.y);
            }
        }
        __syncthreads();
    }

    if (warpM == (warpN >> 1)) {
        const int h = hp * 2 + warpM;
        float* cp = g_ctx + (size_t)(b * Hn + h) * 64 * 64;
#pragma unroll
        for (int mf = 0; mf < 4; mf++) {
            const int d0 = mf * 16 + g;
#pragma unroll
            for (int nf = 0; nf < 4; nf++) {
                const int e0 = (warpN & 1) * 32 + nf * 8 + 2 * t4;
                atomicAdd(cp + (size_t)d0 * 64 + e0, acc[mf][nf][0]);
                atomicAdd(cp + (size_t)d0 * 64 + e0 + 1, acc[mf][nf][1]);
                atomicAdd(cp + (size_t)(d0 + 8) * 64 + e0, acc[mf][nf][2]);
                atomicAdd(cp + (size_t)(d0 + 8) * 64 + e0 + 1, acc[mf][nf][3]);
            }
        }
    }
}

// ---------------- weff (f32 ctx/256 in, fp16 out) ----------------
__global__ __launch_bounds__(256) void weff_kernel(const float* __restrict__ wout) {
    __shared__ float Ws[64][65];
    __shared__ float Cs[64][68];
    const int b = blockIdx.z, h = blockIdx.y, o0 = blockIdx.x * 64;
    const int tid = threadIdx.x;
    const int rr = tid >> 2;
    const int q4 = (tid & 3) * 16;
    const float* wp = wout + (size_t)(o0 + rr) * Dn + h * 64 + q4;
#pragma unroll
    for (int j = 0; j < 16; j += 4) {
        float4 t4v = *(const float4*)(wp + j);
        Ws[q4 + j + 0][rr] = t4v.x; Ws[q4 + j + 1][rr] = t4v.y;
        Ws[q4 + j + 2][rr] = t4v.z; Ws[q4 + j + 3][rr] = t4v.w;
    }
    const float* cp = g_ctx + ((size_t)(b * Hn + h) * 64 + rr) * 64 + q4;
#pragma unroll
    for (int j = 0; j < 16; j += 4) {
        float4 c4 = *(const float4*)(cp + j);
        c4.x *= 0.00390625f; c4.y *= 0.00390625f;   // undo x256 k_sm scale
        c4.z *= 0.00390625f; c4.w *= 0.00390625f;
        *(float4*)&Cs[rr][q4 + j] = c4;
    }
    __syncthreads();

    const int oo = tid >> 2, eg = tid & 3;
    float acc[16];
#pragma unroll
    for (int j = 0; j < 16; j++) acc[j] = 0.f;
#pragma unroll 8
    for (int dd = 0; dd < 64; dd++) {
        const float wv = Ws[dd][oo];
#pragma unroll
        for (int j = 0; j < 16; j++) acc[j] = fmaf(wv, Cs[dd][eg * 16 + j], acc[j]);
    }
    __half* op = g_weff16 + (size_t)b * Dn * Dn + (size_t)(o0 + oo) * Dn + h * 64 + eg * 16;
#pragma unroll
    for (int j = 0; j < 16; j += 2)
        *(__half2*)(op + j) = __floats2half2_rn(acc[j], acc[j + 1]);
}

// ---------------- host side ----------------
extern "C" void kernel_launch(void* const* d_in, const int* in_sizes, int n_in,
                              void* d_out, int out_size) {
    const float* x = (const float*)d_in[0];
    const void* masks = d_in[1];
    const float* w_qkv = (const float*)d_in[2];
    const float* w_out = (const float*)d_in[3];
    const float* b_out = (const float*)d_in[4];
    float* out = (float*)d_out;

    void *pX16, *pKV, *pWKV, *pWQT, *pWE, *pM;
    cudaGetSymbolAddress(&pX16, g_x16);
    cudaGetSymbolAddress(&pKV, g_kv16);
    cudaGetSymbolAddress(&pWKV, g_wkv16);
    cudaGetSymbolAddress(&pWQT, g_wqT16);
    cudaGetSymbolAddress(&pWE, g_weff16);
    cudaGetSymbolAddress(&pM, g_M16);

    cudaFuncSetAttribute(gemm16<0>, cudaFuncAttributeMaxDynamicSharedMemorySize, SMH);
    cudaFuncSetAttribute(gemm16<1>, cudaFuncAttributeMaxDynamicSharedMemorySize, SMH);
    cudaFuncSetAttribute(gemm16<2>, cudaFuncAttributeMaxDynamicSharedMemorySize, SMH);
    cudaFuncSetAttribute(ctx16, cudaFuncAttributeMaxDynamicSharedMemorySize, SMC2);

    count_kernel<<<Bn, 256>>>(masks);                    // launch 1
    prep_w16<<<2048, 256>>>((const float4*)w_qkv);       // launch 2
    prep_x16<<<dim3(Ln, Bn), 256>>>((const float4*)x);   // launch 3

    // GEMM1 (launch 4 -> ncu target): k,v = g_wkv16 @ g_x16[b]^T (fp16 out)
    gemm16<0><<<dim3(16, 16, Bn), 512, SMH>>>(
        (const __half*)pWKV, (const __half*)pX16, pKV, nullptr,
        Dn, Ln, (size_t)0, (size_t)Ln * Dn, (size_t)2048 * Ln);

    fill_bias<<<dim3(Ln, Bn), 256>>>((const float4*)b_out, (float4*)out);

    wq_t16<<<dim3(32, 32), 256>>>(w_qkv);

    softmax_kernel<<<dim3(1024, Bn), 256>>>();

    ctx16<<<dim3(8, 16, Bn), 256, SMC2>>>();

    weff_kernel<<<dim3(16, Hn, Bn), 256>>>(w_out);

    // M[b] = 0.125 * Weff[b] @ WqT^T  (fp16 in/out)
    gemm16<2><<<dim3(8, 4, Bn), 512, SMH>>>(
        (const __half*)pWE, (const __half*)pWQT, pM, nullptr,
        Dn, Dn, (size_t)Dn * Dn, (size_t)0, (size_t)Dn * Dn);

    // GEMM2: out rows (scattered via g_idx) = g_x16[b] @ M[b]^T + b_out
    gemm16<1><<<dim3(32, 4, Bn), 512, SMH>>>(
        (const __half*)pX16, (const __half*)pM, out, b_out,
        Dn, Dn, (size_t)Ln * Dn, (size_t)Dn * Dn, (size_t)Ln * Dn);
}

// round 14
// speedup vs baseline: 3.0878x; 1.0736x over previous
#include <cuda_runtime.h>
#include <cuda_fp16.h>
#include <math.h>
#include <cstdint>

#define Bn 8
#define Ln 4096
#define Dn 1024
#define Hn 16

// ---------------- scratch (static device globals; no allocation) ----------------
__device__ __align__(256) __half g_x16[(size_t)Bn * Ln * Dn];     // compacted+rounded x (fp16)
__device__ __align__(256) __half g_kv16[(size_t)Bn * 2048 * Ln];  // k rows [0,1024), v rows [1024,2048)
__device__ __align__(256) __half g_wkv16[(size_t)2048 * Dn];      // w_qkv rows 1024..3071 (fp16)
__device__ __align__(256) __half g_wqT16[(size_t)Dn * Dn];        // Wq^T (d,c) fp16
__device__ __align__(256) __half g_weff16[(size_t)Bn * Dn * Dn];  // Weff fp16
__device__ __align__(256) __half g_M16[(size_t)Bn * Dn * Dn];     // M = 0.125*Weff@Wq fp16
__device__ __align__(256) float  g_ctx[Bn * Hn * 64 * 64];        // f32 accumulator (x256 scaled)
__device__ int g_idx[Bn][Ln];
__device__ int g_rank[Bn][Ln];
__device__ int g_Lc[Bn];
__device__ int g_Lcp256[Bn];
__device__ int g_Lcp128[Bn];

// ---------------- helpers ----------------
__device__ __forceinline__ uint32_t smem_u32(const void* p) {
    uint32_t a;
    asm("{ .reg .u64 t; cvta.to.shared.u64 t, %1; cvt.u32.u64 %0, t; }" : "=r"(a) : "l"(p));
    return a;
}
__device__ __forceinline__ void cpasync16(uint32_t dst, const void* src) {
    asm volatile("cp.async.cg.shared.global [%0], [%1], 16;" :: "r"(dst), "l"(src) : "memory");
}
#define CP_COMMIT() asm volatile("cp.async.commit_group;" ::: "memory")
#define CP_WAIT1()  asm volatile("cp.async.wait_group 1;" ::: "memory")
#define CP_WAIT0()  asm volatile("cp.async.wait_group 0;" ::: "memory")

__device__ __forceinline__ void mma16(float* c, uint32_t a0, uint32_t a1, uint32_t a2, uint32_t a3,
                                      uint32_t b0, uint32_t b1) {
    asm volatile("mma.sync.aligned.m16n8k16.row.col.f32.f16.f16.f32 "
        "{%0,%1,%2,%3}, {%4,%5,%6,%7}, {%8,%9}, {%0,%1,%2,%3};"
        : "+f"(c[0]), "+f"(c[1]), "+f"(c[2]), "+f"(c[3])
        : "r"(a0), "r"(a1), "r"(a2), "r"(a3), "r"(b0), "r"(b1));
}
__device__ __forceinline__ void ldsm_x4(uint32_t& r0, uint32_t& r1, uint32_t& r2, uint32_t& r3,
                                        uint32_t addr) {
    asm volatile("ldmatrix.sync.aligned.m8n8.x4.shared.b16 {%0,%1,%2,%3}, [%4];"
        : "=r"(r0), "=r"(r1), "=r"(r2), "=r"(r3) : "r"(addr));
}
__device__ __forceinline__ bool mask_at(const void* m, int idx, int u8) {
    if (u8) return ((const unsigned char*)m)[idx] != 0;
    return ((const int*)m)[idx] != 0;
}

// ---------------- count (with fused u8/i32 layout detection) ----------------
__global__ __launch_bounds__(256) void count_kernel(const void* __restrict__ mask) {
    const int b = blockIdx.x, tid = threadIdx.x;
    __shared__ int found;
    if (tid == 0) found = 0;
    __syncthreads();
    {
        const unsigned char* mb = (const unsigned char*)mask;
        int local = 0;
        for (int i = tid; i < 4096; i += 256)
            if ((i & 3) && mb[i]) local = 1;
        if (local) atomicOr(&found, 1);
    }
    __syncthreads();
    const int u8 = found;

    __shared__ int cnt[256];
    __shared__ int excl[257];
    int loc[16], c = 0;
#pragma unroll
    for (int t = 0; t < 16; t++) {
        const int l = tid * 16 + t;
        loc[t] = mask_at(mask, b * Ln + l, u8) ? 0 : 1;
        c += loc[t];
    }
    cnt[tid] = c;
    __syncthreads();
    if (tid == 0) {
        int s = 0;
        for (int i = 0; i < 256; i++) { excl[i] = s; s += cnt[i]; }
        excl[256] = s;
        g_Lc[b] = s;
        g_Lcp256[b] = (s + 255) & ~255;
        g_Lcp128[b] = (s + 127) & ~127;
    }
    __syncthreads();
    int j = excl[tid];
#pragma unroll
    for (int t = 0; t < 16; t++) {
        const int l = tid * 16 + t;
        if (loc[t]) { g_idx[b][j] = l; g_rank[b][l] = j; j++; }
        else g_rank[b][l] = -1;
    }
}

// ---------------- prep: w_kv rows -> fp16; compacted x -> fp16 (zero pad) ----------------
__global__ __launch_bounds__(256) void prep_w16(const float4* __restrict__ w) {
    const int r = blockIdx.x, tid = threadIdx.x;       // r in [0,2048)
    float4 v = w[((size_t)(1024 + r) * Dn + tid * 4) >> 2];
    __half* p = g_wkv16 + (size_t)r * Dn + tid * 4;
    *(__half2*)p = __floats2half2_rn(v.x, v.y);
    *(__half2*)(p + 2) = __floats2half2_rn(v.z, v.w);
}

__global__ __launch_bounds__(256) void prep_x16(const float4* __restrict__ x) {
    const int b = blockIdx.y, j = blockIdx.x, tid = threadIdx.x;
    if (j >= g_Lcp256[b]) return;
    __half* dst = g_x16 + ((size_t)b * Ln + j) * Dn + tid * 4;
    if (j >= g_Lc[b]) {
        *(__half2*)dst = __floats2half2_rn(0.f, 0.f);
        *(__half2*)(dst + 2) = __floats2half2_rn(0.f, 0.f);
        return;
    }
    const int l = g_idx[b][j];
    float4 v = x[((size_t)b * Ln + l) * 256 + tid];
    *(__half2*)dst = __floats2half2_rn(v.x, v.y);
    *(__half2*)(dst + 2) = __floats2half2_rn(v.z, v.w);
}

// ---------------- WqT16 ----------------
__global__ __launch_bounds__(256) void wq_t16(const float* __restrict__ w) {
    __shared__ float t[32][33];
    const int c0 = blockIdx.x * 32, d0 = blockIdx.y * 32;
    const int tx = threadIdx.x & 31, ty = threadIdx.x >> 5;
#pragma unroll
    for (int k = 0; k < 4; k++)
        t[ty + 8 * k][tx] = w[(size_t)(c0 + ty + 8 * k) * Dn + d0 + tx];
    __syncthreads();
#pragma unroll
    for (int k = 0; k < 4; k++)
        g_wqT16[(size_t)(d0 + ty + 8 * k) * Dn + c0 + tx] = __float2half_rn(t[tx][ty + 8 * k]);
}

// ---------------- fp16 GEMM with ldmatrix: C(M x N) = A(M x K) @ B(N x K)^T ----------------
// Tiles 128x256x64, 512 threads (16 warps, warp tile 64x32), 3-stage pipeline,
// ldmatrix.x4 fragment loads, row stride 72 halfs (144B: ldmatrix conflict-free).
// MODE 0: n-guard Lcp256, fp16 out.  MODE 1: m-guard Lcp128, f32 out+bias+scatter.
// MODE 2: no guard, fp16 out * 0.125.
#define RH 72
#define STH ((128 + 256) * RH)    // 27648 halfs / stage
#define NSTH 3
#define SMH (NSTH * STH * 2)      // 165888 B

template <int MODE>
__global__ __launch_bounds__(512, 1) void gemm16(
    const __half* __restrict__ Aall, const __half* __restrict__ Ball,
    void* __restrict__ Call, const float* __restrict__ bias,
    int K, int ldc, size_t bsA, size_t bsB, size_t bsC) {
    const int b = blockIdx.z;
    const int m0 = blockIdx.x * 128, n0 = blockIdx.y * 256;
    if (MODE == 0) { if (n0 >= g_Lcp256[b]) return; }
    if (MODE == 1) { if (m0 >= g_Lcp128[b]) return; }

    extern __shared__ __half smh[];
    const uint32_t smb = smem_u32(smh);
    const int tid = threadIdx.x, lane = tid & 31, wid = tid >> 5;
    const __half* A = Aall + bsA * b;
    const __half* Bp = Ball + bsB * b;

    const int g = lane >> 2, t4 = lane & 3;
    const int warpM = wid & 1, warpN = wid >> 1;      // 2 x 8 warps
    const int mrow0 = warpM * 64, ncol0 = warpN * 32;

    // ldmatrix per-thread address offsets (in halfs, within a stage)
    const int r8 = lane & 7, sel = lane >> 3;
    uint32_t offA[4], offB[2];
#pragma unroll
    for (int mf = 0; mf < 4; mf++)
        offA[mf] = (uint32_t)((mrow0 + mf * 16 + (sel & 1) * 8 + r8) * RH + (sel >> 1) * 8);
#pragma unroll
    for (int p = 0; p < 2; p++)
        offB[p] = (uint32_t)((128 + ncol0 + p * 16 + (lane >> 4) * 8 + r8) * RH + ((lane >> 3) & 1) * 8);

    float acc[4][4][4];
#pragma unroll
    for (int mf = 0; mf < 4; mf++)
#pragma unroll
        for (int nf = 0; nf < 4; nf++)
#pragma unroll
            for (int j = 0; j < 4; j++) acc[mf][nf][j] = 0.f;

    auto load_stage = [&](int s, int ko) {
        const uint32_t sb = smb + (uint32_t)(s * STH) * 2;
        {   // A: 128 rows x 64 halfs, 4 threads/row, 32B each
            const int row = tid >> 2, ch = (tid & 3) * 16;
            const __half* src = A + (size_t)(m0 + row) * K + ko + ch;
            const uint32_t dst = sb + (uint32_t)(row * RH + ch) * 2;
            cpasync16(dst, src);
            cpasync16(dst + 16, src + 8);
        }
        {   // B: 256 rows x 64 halfs, 2 threads/row, 64B each
            const int row = tid & 255, kh = (tid >> 8) * 32;
            const __half* src = Bp + (size_t)(n0 + row) * K + ko + kh;
            const uint32_t dst = sb + (uint32_t)((128 + row) * RH + kh) * 2;
#pragma unroll
            for (int j = 0; j < 4; j++) cpasync16(dst + j * 16, src + j * 8);
        }
    };

    const int NIT = K >> 6;
    load_stage(0, 0);  CP_COMMIT();
    load_stage(1, 64); CP_COMMIT();

    for (int i = 0; i < NIT; i++) {
        CP_WAIT1();
        __syncthreads();
        if (i + 2 < NIT) load_stage((i + 2) % NSTH, (i + 2) * 64);
        CP_COMMIT();

        const uint32_t sbase = smb + (uint32_t)((i % NSTH) * STH) * 2;
#pragma unroll
        for (int ks = 0; ks < 64; ks += 16) {
            uint32_t a[4][4];
#pragma unroll
            for (int mf = 0; mf < 4; mf++)
                ldsm_x4(a[mf][0], a[mf][1], a[mf][2], a[mf][3],
                        sbase + (offA[mf] + ks) * 2);
            uint32_t bfrag[2][4];   // [pair][b0A,b1A,b0B,b1B]
#pragma unroll
            for (int p = 0; p < 2; p++)
                ldsm_x4(bfrag[p][0], bfrag[p][1], bfrag[p][2], bfrag[p][3],
                        sbase + (offB[p] + ks) * 2);
#pragma unroll
            for (int nf = 0; nf < 4; nf++) {
                const uint32_t b0 = bfrag[nf >> 1][(nf & 1) * 2];
                const uint32_t b1 = bfrag[nf >> 1][(nf & 1) * 2 + 1];
#pragma unroll
                for (int mf = 0; mf < 4; mf++)
                    mma16(acc[mf][nf], a[mf][0], a[mf][1], a[mf][2], a[mf][3], b0, b1);
            }
        }
    }

    if (MODE == 0 || MODE == 2) {
        __half* Ch = (__half*)Call + bsC * b;
        const float sc = (MODE == 2) ? 0.125f : 1.0f;
#pragma unroll
        for (int mf = 0; mf < 4; mf++) {
            const int r0 = m0 + mrow0 + mf * 16 + g;
#pragma unroll
            for (int nf = 0; nf < 4; nf++) {
                const int c0 = n0 + ncol0 + nf * 8 + 2 * t4;
                *(__half2*)(Ch + (size_t)r0 * ldc + c0) =
                    __floats2half2_rn(sc * acc[mf][nf][0], sc * acc[mf][nf][1]);
                *(__half2*)(Ch + (size_t)(r0 + 8) * ldc + c0) =
                    __floats2half2_rn(sc * acc[mf][nf][2], sc * acc[mf][nf][3]);
            }
        }
    } else {
        float* C = (float*)Call + bsC * b;
        const int lc = g_Lc[b];
#pragma unroll
        for (int mf = 0; mf < 4; mf++) {
            const int r0 = m0 + mrow0 + mf * 16 + g;
            const int la = (r0 < lc) ? g_idx[b][r0] : -1;
            const int lb2 = (r0 + 8 < lc) ? g_idx[b][r0 + 8] : -1;
#pragma unroll
            for (int nf = 0; nf < 4; nf++) {
                const int c0 = n0 + ncol0 + nf * 8 + 2 * t4;
                const float2 bb = *(const float2*)(bias + c0);
                if (la >= 0)
                    *(float2*)(C + (size_t)la * ldc + c0) =
                        make_float2(acc[mf][nf][0] + bb.x, acc[mf][nf][1] + bb.y);
                if (lb2 >= 0)
                    *(float2*)(C + (size_t)lb2 * ldc + c0) =
                        make_float2(acc[mf][nf][2] + bb.x, acc[mf][nf][3] + bb.y);
            }
        }
    }
}

// ---------------- fill masked rows of out with bias ----------------
__global__ __launch_bounds__(256) void fill_bias(const float4* __restrict__ bout,
                                                 float4* __restrict__ out) {
    const int b = blockIdx.y, l = blockIdx.x, tid = threadIdx.x;
    if (g_rank[b][l] >= 0) return;
    out[((size_t)b * Ln + l) * 256 + tid] = bout[tid];
}

// ---------------- softmax on k rows (fp16 in/out, x256 scale); zeroes g_ctx ----------------
__global__ __launch_bounds__(256) void softmax_kernel() {
    const int b = blockIdx.y, r = blockIdx.x;
    const int tid = threadIdx.x;
    {
        const int gid = ((blockIdx.y * 1024 + blockIdx.x) << 8) + tid;
        if (gid < Bn * Hn * 64 * 64) g_ctx[gid] = 0.f;
    }
    const int lc = g_Lc[b], lcp = g_Lcp256[b];
    __half* rowp = g_kv16 + (size_t)b * 2048 * Ln + (size_t)r * Ln;
    float sum = 0.f;
    for (int l = tid; l < lc; l += 256) sum += expf(__half2float(rowp[l]));
    __shared__ float red[256];
    red[tid] = sum;
    __syncthreads();
    for (int s = 128; s > 0; s >>= 1) {
        if (tid < s) red[tid] += red[tid + s];
        __syncthreads();
    }
    const float inv = 256.f / red[0];   // x256: keeps k_sm in fp16 normal range
    for (int l = tid; l < lcp; l += 256)
        rowp[l] = (l < lc) ? __float2half_rn(expf(__half2float(rowp[l])) * inv)
                           : __float2half_rn(0.f);
}

// ---------------- context fp16 (LDS path, own stride 80) ----------------
#define RC 80
#define CSTH (2 * 128 * RC)
#define SMC2 (2 * CSTH * 2)      // 81920 B

__global__ __launch_bounds__(256, 2) void ctx16() {
    const int b = blockIdx.z, hp = blockIdx.x, ch = blockIdx.y;
    const int l0 = ch * 256;
    if (l0 >= g_Lcp256[b]) return;

    extern __shared__ __half smh[];
    const uint32_t smb = smem_u32(smh);
    const int tid = threadIdx.x, lane = tid & 31, wid = tid >> 5;
    const __half* A = g_kv16 + (size_t)b * 2048 * Ln + (size_t)(hp * 128) * Ln + l0;
    const __half* Bp = g_kv16 + (size_t)b * 2048 * Ln + (size_t)(1024 + hp * 128) * Ln + l0;

    const int g = lane >> 2, t4 = lane & 3;
    const int warpM = wid & 1, warpN = wid >> 1;
    const int mrow0 = warpM * 64, ncol0 = warpN * 32;

    float acc[4][4][4];
#pragma unroll
    for (int mf = 0; mf < 4; mf++)
#pragma unroll
        for (int nf = 0; nf < 4; nf++)
#pragma unroll
            for (int j = 0; j < 4; j++) acc[mf][nf][j] = 0.f;

    auto load_stage = [&](int s, int ko) {
        const uint32_t sb = smb + (uint32_t)(s * CSTH) * 2;
        const int row = tid >> 1, kh = (tid & 1) * 32;
        const __half* srcA = A + (size_t)row * Ln + ko + kh;
        const __half* srcB = Bp + (size_t)row * Ln + ko + kh;
        const uint32_t dA = sb + (uint32_t)(row * RC + kh) * 2;
        const uint32_t dB = sb + (uint32_t)((128 + row) * RC + kh) * 2;
#pragma unroll
        for (int j = 0; j < 4; j++) {
            cpasync16(dA + j * 16, srcA + j * 8);
            cpasync16(dB + j * 16, srcB + j * 8);
        }
    };

    const int NIT = 4;
    load_stage(0, 0);
    CP_COMMIT();

    for (int i = 0; i < NIT; i++) {
        if (i + 1 < NIT) { load_stage((i + 1) & 1, (i + 1) * 64); CP_COMMIT(); CP_WAIT1(); }
        else             { CP_WAIT0(); }
        __syncthreads();

        const __half* As = smh + (i & 1) * CSTH;
        const __half* Bs = As + 128 * RC;
#pragma unroll
        for (int ks = 0; ks < 64; ks += 16) {
            uint2 aLo[4], aHi[4];
#pragma unroll
            for (int mf = 0; mf < 4; mf++) {
                const __half* ap = As + (mrow0 + mf * 16 + g) * RC + ks + 4 * t4;
                aLo[mf] = *(const uint2*)ap;
                aHi[mf] = *(const uint2*)(ap + 8 * RC);
            }
#pragma unroll
            for (int nf = 0; nf < 4; nf++) {
                const uint2 bv = *(const uint2*)(Bs + (ncol0 + nf * 8 + g) * RC + ks + 4 * t4);
#pragma unroll
                for (int mf = 0; mf < 4; mf++)
                    mma16(acc[mf][nf], aLo[mf].x, aHi[mf].x, aLo[mf].y, aHi[mf].y, bv.x, bv.y);
            }
        }
        __syncthreads();
    }

    if (warpM == (warpN >> 1)) {
        const int h = hp * 2 + warpM;
        float* cp = g_ctx + (size_t)(b * Hn + h) * 64 * 64;
#pragma unroll
        for (int mf = 0; mf < 4; mf++) {
            const int d0 = mf * 16 + g;
#pragma unroll
            for (int nf = 0; nf < 4; nf++) {
                const int e0 = (warpN & 1) * 32 + nf * 8 + 2 * t4;
                atomicAdd(cp + (size_t)d0 * 64 + e0, acc[mf][nf][0]);
                atomicAdd(cp + (size_t)d0 * 64 + e0 + 1, acc[mf][nf][1]);
                atomicAdd(cp + (size_t)(d0 + 8) * 64 + e0, acc[mf][nf][2]);
                atomicAdd(cp + (size_t)(d0 + 8) * 64 + e0 + 1, acc[mf][nf][3]);
            }
        }
    }
}

// ---------------- weff (f32 ctx/256 in, fp16 out) ----------------
__global__ __launch_bounds__(256) void weff_kernel(const float* __restrict__ wout) {
    __shared__ float Ws[64][65];
    __shared__ float Cs[64][68];
    const int b = blockIdx.z, h = blockIdx.y, o0 = blockIdx.x * 64;
    const int tid = threadIdx.x;
    const int rr = tid >> 2;
    const int q4 = (tid & 3) * 16;
    const float* wp = wout + (size_t)(o0 + rr) * Dn + h * 64 + q4;
#pragma unroll
    for (int j = 0; j < 16; j += 4) {
        float4 t4v = *(const float4*)(wp + j);
        Ws[q4 + j + 0][rr] = t4v.x; Ws[q4 + j + 1][rr] = t4v.y;
        Ws[q4 + j + 2][rr] = t4v.z; Ws[q4 + j + 3][rr] = t4v.w;
    }
    const float* cp = g_ctx + ((size_t)(b * Hn + h) * 64 + rr) * 64 + q4;
#pragma unroll
    for (int j = 0; j < 16; j += 4) {
        float4 c4 = *(const float4*)(cp + j);
        c4.x *= 0.00390625f; c4.y *= 0.00390625f;
        c4.z *= 0.00390625f; c4.w *= 0.00390625f;
        *(float4*)&Cs[rr][q4 + j] = c4;
    }
    __syncthreads();

    const int oo = tid >> 2, eg = tid & 3;
    float acc[16];
#pragma unroll
    for (int j = 0; j < 16; j++) acc[j] = 0.f;
#pragma unroll 8
    for (int dd = 0; dd < 64; dd++) {
        const float wv = Ws[dd][oo];
#pragma unroll
        for (int j = 0; j < 16; j++) acc[j] = fmaf(wv, Cs[dd][eg * 16 + j], acc[j]);
    }
    __half* op = g_weff16 + (size_t)b * Dn * Dn + (size_t)(o0 + oo) * Dn + h * 64 + eg * 16;
#pragma unroll
    for (int j = 0; j < 16; j += 2)
        *(__half2*)(op + j) = __floats2half2_rn(acc[j], acc[j + 1]);
}

// ---------------- host side ----------------
extern "C" void kernel_launch(void* const* d_in, const int* in_sizes, int n_in,
                              void* d_out, int out_size) {
    const float* x = (const float*)d_in[0];
    const void* masks = d_in[1];
    const float* w_qkv = (const float*)d_in[2];
    const float* w_out = (const float*)d_in[3];
    const float* b_out = (const float*)d_in[4];
    float* out = (float*)d_out;

    void *pX16, *pKV, *pWKV, *pWQT, *pWE, *pM;
    cudaGetSymbolAddress(&pX16, g_x16);
    cudaGetSymbolAddress(&pKV, g_kv16);
    cudaGetSymbolAddress(&pWKV, g_wkv16);
    cudaGetSymbolAddress(&pWQT, g_wqT16);
    cudaGetSymbolAddress(&pWE, g_weff16);
    cudaGetSymbolAddress(&pM, g_M16);

    cudaFuncSetAttribute(gemm16<0>, cudaFuncAttributeMaxDynamicSharedMemorySize, SMH);
    cudaFuncSetAttribute(gemm16<1>, cudaFuncAttributeMaxDynamicSharedMemorySize, SMH);
    cudaFuncSetAttribute(gemm16<2>, cudaFuncAttributeMaxDynamicSharedMemorySize, SMH);
    cudaFuncSetAttribute(ctx16, cudaFuncAttributeMaxDynamicSharedMemorySize, SMC2);

    count_kernel<<<Bn, 256>>>(masks);                    // launch 1
    prep_w16<<<2048, 256>>>((const float4*)w_qkv);       // launch 2
    prep_x16<<<dim3(Ln, Bn), 256>>>((const float4*)x);   // launch 3

    // GEMM1 (launch 4 -> ncu target): k,v = g_wkv16 @ g_x16[b]^T (fp16 out)
    gemm16<0><<<dim3(16, 16, Bn), 512, SMH>>>(
        (const __half*)pWKV, (const __half*)pX16, pKV, nullptr,
        Dn, Ln, (size_t)0, (size_t)Ln * Dn, (size_t)2048 * Ln);

    fill_bias<<<dim3(Ln, Bn), 256>>>((const float4*)b_out, (float4*)out);

    wq_t16<<<dim3(32, 32), 256>>>(w_qkv);

    softmax_kernel<<<dim3(1024, Bn), 256>>>();

    ctx16<<<dim3(8, 16, Bn), 256, SMC2>>>();

    weff_kernel<<<dim3(16, Hn, Bn), 256>>>(w_out);

    // M[b] = 0.125 * Weff[b] @ WqT^T  (fp16 in/out)
    gemm16<2><<<dim3(8, 4, Bn), 512, SMH>>>(
        (const __half*)pWE, (const __half*)pWQT, pM, nullptr,
        Dn, Dn, (size_t)Dn * Dn, (size_t)0, (size_t)Dn * Dn);

    // GEMM2: out rows (scattered via g_idx) = g_x16[b] @ M[b]^T + b_out
    gemm16<1><<<dim3(32, 4, Bn), 512, SMH>>>(
        (const __half*)pX16, (const __half*)pM, out, b_out,
        Dn, Dn, (size_t)Ln * Dn, (size_t)Dn * Dn, (size_t)Ln * Dn);
}